// round 11
// baseline (speedup 1.0000x reference)
#include <cuda_runtime.h>
#include <cuda_fp16.h>
#include <cstdint>
#include <math.h>

#define H     1024
#define BATCH 64
#define TENC  128
#define TDEC  64
#define VOCAB 32000
#define DEMB  512

// ---------------- persistent-GRU (128 CTAs x 8 units) smem layout ----------------
#define GRU_NCTA 128
#define W2S 516                       // half2 words per Whh row (512 + 4 pad)
#define A2S 68                        // half2 words per h-chunk row (64 + 4 pad)
#define G2S 28                        // fp32 per partial row (24 + 4 pad)
#define GRU_SMEM_WORDS (24 * W2S + 2 * 64 * A2S)
#define GRU_SMEM_BYTES (GRU_SMEM_WORDS * 4)

// ---------------- fp16 GEMM smem: BM128 x BN256 x BK64, padded 144B rows ----------------
// stage: A 128 rows * 144B (18432) + B 256 rows * 144B (36864) = 55296 B
#define GROW 144
#define GA_BYTES (128 * GROW)
#define GSTG (GA_BYTES + 256 * GROW)
#define GEMM_SMEM_BYTES (3 * GSTG + 64)   // + mbarriers
#define GSTG_TX (384 * 128)               // bytes per stage = 49152

// ---------------- scratch ----------------
__device__ __half g_Xe[(size_t)TENC * BATCH * DEMB];
__device__ float  g_Xi[(size_t)TENC * BATCH * 3 * H];
__device__ __half g_Xw[(size_t)TDEC * BATCH * DEMB];
__device__ float  g_Xd[(size_t)TDEC * BATCH * 3 * H];
__device__ float  g_ctx[(size_t)BATCH * 3 * H];
__device__ float  g_h0f[(size_t)BATCH * H];
__device__ float  g_h1f[(size_t)BATCH * H];
__device__ __half g_h0h[(size_t)BATCH * H];
__device__ __half g_h1h[(size_t)BATCH * H];
__device__ float  g_hd0f[(size_t)BATCH * H];
__device__ float  g_hd1f[(size_t)BATCH * H];
__device__ __half g_hd0h[(size_t)BATCH * H];
__device__ __half g_hd1h[(size_t)BATCH * H];
__device__ __half g_st[(size_t)TDEC * BATCH * H];
__device__ __half g_We[(size_t)3 * H * DEMB];
__device__ __half g_Wd[(size_t)3 * H * DEMB];
__device__ __half g_Wl[(size_t)VOCAB * H];
__device__ unsigned g_bar_cnt;
__device__ unsigned g_bar_gen;

// ---------------- helpers ----------------
__device__ __forceinline__ uint32_t pack2(float x, float y) {
    __half2 h = __floats2half2_rn(x, y);
    return *(uint32_t*)&h;
}
__device__ __forceinline__ uint32_t f2tf32(float f) {
    uint32_t r;
    asm("cvt.rna.tf32.f32 %0, %1;" : "=r"(r) : "f"(f));
    return r;
}
__device__ __forceinline__ void cvt_store4(uint32_t* dst, float4 v) {
    dst[0] = f2tf32(v.x); dst[1] = f2tf32(v.y);
    dst[2] = f2tf32(v.z); dst[3] = f2tf32(v.w);
}
__device__ __forceinline__ void mma_f16(float* c, const uint32_t* a, const uint32_t* b) {
    asm volatile(
        "mma.sync.aligned.m16n8k16.row.col.f32.f16.f16.f32 "
        "{%0,%1,%2,%3}, {%4,%5,%6,%7}, {%8,%9}, {%0,%1,%2,%3};\n"
        : "+f"(c[0]), "+f"(c[1]), "+f"(c[2]), "+f"(c[3])
        : "r"(a[0]), "r"(a[1]), "r"(a[2]), "r"(a[3]), "r"(b[0]), "r"(b[1]));
}
__device__ __forceinline__ void mma_tf32(float* c, const uint32_t* a, const uint32_t* b) {
    asm volatile(
        "mma.sync.aligned.m16n8k8.row.col.f32.tf32.tf32.f32 "
        "{%0,%1,%2,%3}, {%4,%5,%6,%7}, {%8,%9}, {%0,%1,%2,%3};\n"
        : "+f"(c[0]), "+f"(c[1]), "+f"(c[2]), "+f"(c[3])
        : "r"(a[0]), "r"(a[1]), "r"(a[2]), "r"(a[3]), "r"(b[0]), "r"(b[1]));
}
__device__ __forceinline__ uint32_t smem_u32(const void* p) {
    uint32_t a;
    asm("{ .reg .u64 t; cvta.to.shared.u64 t, %1; cvt.u32.u64 %0, t; }" : "=r"(a) : "l"(p));
    return a;
}
// 128-byte bulk async copy gmem->smem with mbarrier tx completion (sm_90 base)
__device__ __forceinline__ void bulk128(uint32_t dst, const void* src, uint32_t mbar) {
    asm volatile(
        "cp.async.bulk.shared::cluster.global.mbarrier::complete_tx::bytes [%0], [%1], %2, [%3];"
        :: "r"(dst), "l"(src), "r"(128u), "r"(mbar) : "memory");
}
#define MBARRIER_INIT(mbar, count) \
    asm volatile("mbarrier.init.shared.b64 [%0], %1;" :: "r"((uint32_t)(mbar)), "r"((uint32_t)(count)) : "memory")
#define MBARRIER_EXPECT_TX(mbar, tx) \
    asm volatile("mbarrier.arrive.expect_tx.shared.b64 _, [%0], %1;" :: "r"((uint32_t)(mbar)), "r"((uint32_t)(tx)) : "memory")
#define MBARRIER_WAIT_PARITY(mbar, parity) do { \
    uint32_t _m = (uint32_t)(mbar); uint32_t _p = (uint32_t)(parity); uint32_t _d; \
    asm volatile("{\n\t.reg .pred p;\n\t" \
        "mbarrier.try_wait.parity.acquire.cta.shared::cta.b64 p, [%1], %2;\n\t" \
        "selp.b32 %0, 1, 0, p;\n\t}" : "=r"(_d) : "r"(_m), "r"(_p) : "memory"); \
    if (!_d) { \
        asm volatile("{\n\t.reg .pred P1;\n\t" \
            "WL_%=:\n\t" \
            "mbarrier.try_wait.parity.acquire.cta.shared::cta.b64 P1, [%0], %1, 0x989680;\n\t" \
            "@P1 bra.uni WD_%=;\n\t" \
            "bra.uni WL_%=;\n\t" \
            "WD_%=:\n\t}" :: "r"(_m), "r"(_p) : "memory"); \
    } \
} while (0)
#define LDSM4(r0, r1, r2, r3, addr) \
    asm volatile("ldmatrix.sync.aligned.m8n8.x4.shared.b16 {%0,%1,%2,%3}, [%4];" \
                 : "=r"(r0), "=r"(r1), "=r"(r2), "=r"(r3) : "r"(addr))

// ---------------- weight fp16 conversion ----------------
__global__ void conv_k(const float* __restrict__ src, __half* __restrict__ dst, int n8) {
    int i = blockIdx.x * 256 + threadIdx.x;
    if (i < n8) {
        float4 a = ((const float4*)src)[2 * i];
        float4 b = ((const float4*)src)[2 * i + 1];
        uint4 u;
        u.x = pack2(a.x, a.y); u.y = pack2(a.z, a.w);
        u.z = pack2(b.x, b.y); u.w = pack2(b.z, b.w);
        ((uint4*)dst)[i] = u;
    }
}
__global__ void conv_slice_k(const float* __restrict__ src, __half* __restrict__ dst) {
    int r = blockIdx.x;
    float4 v = ((const float4*)(src + (size_t)r * (DEMB + H)))[threadIdx.x];
    uint2 u; u.x = pack2(v.x, v.y); u.y = pack2(v.z, v.w);
    ((uint2*)(dst + (size_t)r * DEMB))[threadIdx.x] = u;
}

// ---------------- embedding gathers -> fp16 ----------------
__global__ void embed_enc_k(const int* __restrict__ x, const float* __restrict__ emb,
                            __half* __restrict__ Xe) {
    int row = blockIdx.x;
    int t = row >> 6, b = row & 63;
    int tok = x[b * TENC + t];
    float4 v = ((const float4*)(emb + (size_t)tok * DEMB))[threadIdx.x];
    uint2 u; u.x = pack2(v.x, v.y); u.y = pack2(v.z, v.w);
    ((uint2*)(Xe + (size_t)row * DEMB))[threadIdx.x] = u;
}
__global__ void embed_dec_k(const int* __restrict__ labels, const int* __restrict__ bos,
                            const float* __restrict__ emb, __half* __restrict__ Xw) {
    int row = blockIdx.x;
    int t = row >> 6, b = row & 63;
    int tok = (t == 0) ? bos[0] : labels[b * TDEC + t - 1];
    float4 v = ((const float4*)(emb + (size_t)tok * DEMB))[threadIdx.x];
    uint2 u; u.x = pack2(v.x, v.y); u.y = pack2(v.z, v.w);
    ((uint2*)(Xw + (size_t)row * DEMB))[threadIdx.x] = u;
}

__global__ void init_all_k(float* __restrict__ h0f, __half* __restrict__ h0h,
                           float* __restrict__ hd0f, __half* __restrict__ hd0h,
                           const float* __restrict__ dec_init) {
    int b = blockIdx.x, u = threadIdx.x;
    h0f[b * H + u] = 0.0f;
    h0h[b * H + u] = __float2half_rn(0.0f);
    float di = dec_init[u];
    hd0f[b * H + u] = di;
    hd0h[b * H + u] = __float2half_rn(di);
    if (b == 0 && u == 0) { g_bar_cnt = 0; g_bar_gen = 0; }
}

// ---------------- fp16 GEMM: C(MxN fp32) = A(MxK h) @ B(NxK h)^T + bias ----------------
// BM=128, BN=256, BK=64. 512 threads (16 warps: wr=wid>>2 m4, wc=wid&3 n4),
// warp tile 32x64. 3-stage cp.async.bulk (128B/row) + mbarrier; padded 144B smem rows
// (row*9 16B-units -> conflict-free ldmatrix without swizzle). 1 CTA/SM.
__global__ __launch_bounds__(512, 1)
void gemm_f16_k(const __half* __restrict__ A, const __half* __restrict__ B,
                const float* __restrict__ bias, float* __restrict__ C,
                int N, int K, int trans_out) {
    extern __shared__ char smc[];
    const uint32_t sb = smem_u32(smc);
    const uint32_t MB = sb + 3 * GSTG;          // mbar[s] at MB + 8*s
    const int m0 = blockIdx.x * 128, n0 = blockIdx.y * 256;
    const int tid = threadIdx.x, lane = tid & 31, wid = tid >> 5;
    const int wr = wid >> 2, wc = wid & 3;
    const int g = lane >> 2, tg = lane & 3;

    float acc[2][8][4];
#pragma unroll
    for (int ms = 0; ms < 2; ms++)
#pragma unroll
        for (int ns = 0; ns < 8; ns++)
#pragma unroll
            for (int i = 0; i < 4; i++) acc[ms][ns][i] = 0.0f;

    const __half* Ab = A + (size_t)m0 * K;
    const __half* Bb = B + (size_t)n0 * K;

    if (tid == 0) {
        MBARRIER_INIT(MB + 0, 1);
        MBARRIER_INIT(MB + 8, 1);
        MBARRIER_INIT(MB + 16, 1);
    }
    __syncthreads();

    // issue one stage: 384 row-copies of 128B, distributed over 16 warps' lane0
    auto issue_stage = [&](int s, int k0) {
        uint32_t sbase = sb + s * GSTG;
        uint32_t mb = MB + s * 8;
        if (tid == 0) MBARRIER_EXPECT_TX(mb, GSTG_TX);
        if (lane == 0) {
            int base = wid * 24;
#pragma unroll 4
            for (int j = 0; j < 24; j++) {
                int r = base + j;
                if (r < 128) {
                    bulk128(sbase + r * GROW, Ab + (size_t)r * K + k0, mb);
                } else {
                    int r2 = r - 128;
                    bulk128(sbase + GA_BYTES + r2 * GROW, Bb + (size_t)r2 * K + k0, mb);
                }
            }
        }
    };

    const int NT = K >> 6;
    issue_stage(0, 0);
    issue_stage(1, 64);
    issue_stage(2, 128);

    const int r16 = lane & 15, chb = (lane >> 4) << 4;

    for (int it = 0; it < NT; ++it) {
        const int s = it % 3;
        MBARRIER_WAIT_PARITY(MB + s * 8, (it / 3) & 1);

        const uint32_t sA = sb + s * GSTG;
        const uint32_t sB = sA + GA_BYTES;
#pragma unroll
        for (int kk = 0; kk < 4; kk++) {
            const int kb = kk * 32 + chb;
            uint32_t a[2][4], b[8][2];
#pragma unroll
            for (int ms = 0; ms < 2; ms++) {
                uint32_t ad = sA + (wr * 32 + ms * 16 + r16) * GROW + kb;
                LDSM4(a[ms][0], a[ms][1], a[ms][2], a[ms][3], ad);
            }
#pragma unroll
            for (int np = 0; np < 4; np++) {
                uint32_t bd = sB + (wc * 64 + np * 16 + r16) * GROW + kb;
                uint32_t r0, r1, r2, r3;
                LDSM4(r0, r1, r2, r3, bd);
                b[2 * np][0] = r0; b[2 * np + 1][0] = r1;
                b[2 * np][1] = r2; b[2 * np + 1][1] = r3;
            }
#pragma unroll
            for (int ms = 0; ms < 2; ms++)
#pragma unroll
                for (int ns = 0; ns < 8; ns++)
                    mma_f16(acc[ms][ns], a[ms], b[ns]);
        }
        __syncthreads();                 // all warps done with stage s
        if (it + 3 < NT) issue_stage(s, (it + 3) * 64);
    }

#pragma unroll
    for (int ms = 0; ms < 2; ms++)
#pragma unroll
        for (int ns = 0; ns < 8; ns++) {
            int row = m0 + wr * 32 + ms * 16 + g;
            int col = n0 + wc * 64 + ns * 8 + 2 * tg;
            float b0 = bias[col], b1 = bias[col + 1];
#pragma unroll
            for (int h2 = 0; h2 < 2; h2++) {
                int r = row + h2 * 8;
                size_t idx;
                if (trans_out) {
                    int bb = r & 63, tt = r >> 6;
                    idx = ((size_t)bb * TDEC + tt) * (size_t)N + col;
                } else {
                    idx = (size_t)r * (size_t)N + col;
                }
                float2 v;
                v.x = acc[ms][ns][h2 * 2 + 0] + b0;
                v.y = acc[ms][ns][h2 * 2 + 1] + b1;
                *(float2*)(C + idx) = v;
            }
        }
}

// ---------------- small tf32 GEMM (ctx only: 64 x 3072 x 1024) ----------------
__global__ __launch_bounds__(256, 2)
void gemm_tf32_k(const float* __restrict__ A, int lda,
                 const float* __restrict__ W, int ldw, int koff,
                 float* __restrict__ C, int M, int N, int K) {
    __shared__ uint32_t As[128][20];
    __shared__ uint32_t Bs[128][20];
    const int m0 = blockIdx.x * 128, n0 = blockIdx.y * 128;
    const int tid = threadIdx.x, lane = tid & 31, wid = tid >> 5;
    const int wr = wid >> 1, wc = wid & 1;
    const int g = lane >> 2, tg = lane & 3;
    float acc[2][8][4];
#pragma unroll
    for (int ms = 0; ms < 2; ms++)
#pragma unroll
        for (int ns = 0; ns < 8; ns++)
#pragma unroll
            for (int i = 0; i < 4; i++) acc[ms][ns][i] = 0.0f;
    const int lrow = tid >> 1, lcol = (tid & 1) * 8;
    const float* Ap = A + (size_t)(m0 + lrow) * lda + lcol;
    const float* Wp = W + (size_t)(n0 + lrow) * ldw + koff + lcol;
    const bool aok = (m0 + lrow) < M;
    for (int k0 = 0; k0 < K; k0 += 16) {
        if (aok) {
            cvt_store4(&As[lrow][lcol], *(const float4*)(Ap + k0));
            cvt_store4(&As[lrow][lcol + 4], *(const float4*)(Ap + k0 + 4));
        } else {
#pragma unroll
            for (int i = 0; i < 8; i++) As[lrow][lcol + i] = 0u;
        }
        cvt_store4(&Bs[lrow][lcol], *(const float4*)(Wp + k0));
        cvt_store4(&Bs[lrow][lcol + 4], *(const float4*)(Wp + k0 + 4));
        __syncthreads();
#pragma unroll
        for (int kk = 0; kk < 16; kk += 8) {
            uint32_t a[2][4], b[8][2];
#pragma unroll
            for (int ms = 0; ms < 2; ms++) {
                int r0 = wr * 32 + ms * 16 + g;
                a[ms][0] = As[r0][kk + tg]; a[ms][1] = As[r0 + 8][kk + tg];
                a[ms][2] = As[r0][kk + tg + 4]; a[ms][3] = As[r0 + 8][kk + tg + 4];
            }
#pragma unroll
            for (int ns = 0; ns < 8; ns++) {
                int br = wc * 64 + ns * 8 + g;
                b[ns][0] = Bs[br][kk + tg]; b[ns][1] = Bs[br][kk + tg + 4];
            }
#pragma unroll
            for (int ms = 0; ms < 2; ms++)
#pragma unroll
                for (int ns = 0; ns < 8; ns++) mma_tf32(acc[ms][ns], a[ms], b[ns]);
        }
        __syncthreads();
    }
#pragma unroll
    for (int ms = 0; ms < 2; ms++)
#pragma unroll
        for (int ns = 0; ns < 8; ns++) {
            int row = m0 + wr * 32 + ms * 16 + g;
            int col = n0 + wc * 64 + ns * 8 + 2 * tg;
#pragma unroll
            for (int h2 = 0; h2 < 2; h2++) {
                int r = row + h2 * 8;
                if (r < M) {
                    size_t idx = (size_t)r * (size_t)N + col;
                    float2 v;
                    v.x = acc[ms][ns][h2 * 2 + 0];
                    v.y = acc[ms][ns][h2 * 2 + 1];
                    *(float2*)(C + idx) = v;
                }
            }
        }
}

// ---------------- persistent GRU recurrence: 128 CTAs x 8 hidden units ----------------
// ctx_r/ctx_z fold into sigmoid biases; ctx_n stays OUTSIDE the r*() product.
template <bool DEC>
__global__ __launch_bounds__(256, 1)
void gru_persistent_k(float* __restrict__ h0f, float* __restrict__ h1f,
                      __half* __restrict__ h0h, __half* __restrict__ h1h,
                      const float* __restrict__ Whh, const float* __restrict__ bhh,
                      const float* __restrict__ gi, const float* __restrict__ ctx,
                      __half* __restrict__ st, int T) {
    extern __shared__ uint32_t sm[];
    uint32_t* Wsh = sm;
    uint32_t* Ash = sm + 24 * W2S;
    float* Gsh = (float*)(sm + 24 * W2S);

    const int u0 = blockIdx.x * 8;
    const int tid = threadIdx.x, lane = tid & 31, wid = tid >> 5;
    const int kg = wid >> 1, mg = wid & 1;
    const int g = lane >> 2, tg = lane & 3;

    for (int j = 0; j < 24; j++) {
        int grow = (j >> 3) * H + u0 + (j & 7);
        float4 v = *(const float4*)(Whh + (size_t)grow * H + tid * 4);
        Wsh[j * W2S + tid * 2]     = pack2(v.x, v.y);
        Wsh[j * W2S + tid * 2 + 1] = pack2(v.z, v.w);
    }
    const int sr = tid >> 2, q = tid & 3;
    const int gb0 = tid >> 3, gu0 = tid & 7;
    const int gb1 = (tid + 256) >> 3, gu1 = (tid + 256) & 7;

    float bR0 = bhh[u0 + gu0], bZ0 = bhh[H + u0 + gu0], bN0 = bhh[2 * H + u0 + gu0];
    float bR1 = bhh[u0 + gu1], bZ1 = bhh[H + u0 + gu1], bN1 = bhh[2 * H + u0 + gu1];
    float cN0 = 0.0f, cN1 = 0.0f;
    if (DEC) {
        bR0 += ctx[(size_t)gb0 * 3 * H + u0 + gu0];
        bZ0 += ctx[(size_t)gb0 * 3 * H + H + u0 + gu0];
        cN0  = ctx[(size_t)gb0 * 3 * H + 2 * H + u0 + gu0];
        bR1 += ctx[(size_t)gb1 * 3 * H + u0 + gu1];
        bZ1 += ctx[(size_t)gb1 * 3 * H + H + u0 + gu1];
        cN1  = ctx[(size_t)gb1 * 3 * H + 2 * H + u0 + gu1];
    }

    for (int t = 0; t < T; t++) {
        const float* hinf = (t & 1) ? h1f : h0f;
        const __half* hinh = (t & 1) ? h1h : h0h;
        float* houtf = (t & 1) ? h0f : h1f;
        __half* houth = (t & 1) ? h0h : h1h;
        const float* gi_t = gi + (size_t)t * BATCH * 3 * H;

        float pR0 = gi_t[(size_t)gb0 * 3 * H + u0 + gu0];
        float pZ0 = gi_t[(size_t)gb0 * 3 * H + H + u0 + gu0];
        float pN0 = gi_t[(size_t)gb0 * 3 * H + 2 * H + u0 + gu0];
        float pR1 = gi_t[(size_t)gb1 * 3 * H + u0 + gu1];
        float pZ1 = gi_t[(size_t)gb1 * 3 * H + H + u0 + gu1];
        float pN1 = gi_t[(size_t)gb1 * 3 * H + 2 * H + u0 + gu1];
        float hc0 = hinf[(size_t)gb0 * H + u0 + gu0];
        float hc1 = hinf[(size_t)gb1 * H + u0 + gu1];

        uint4 p[4];
        {
            const uint4* src = (const uint4*)(hinh + (size_t)sr * H + q * 32);
#pragma unroll
            for (int i = 0; i < 4; i++) p[i] = src[i];
        }

        float acc[2][3][4];
#pragma unroll
        for (int ms = 0; ms < 2; ms++)
#pragma unroll
            for (int ns = 0; ns < 3; ns++)
#pragma unroll
                for (int i = 0; i < 4; i++) acc[ms][ns][i] = 0.0f;

        for (int c = 0; c < 8; c++) {
            uint32_t* Ab = Ash + (c & 1) * 64 * A2S;
            {
                uint4* dst = (uint4*)(Ab + sr * A2S + q * 16);
#pragma unroll
                for (int i = 0; i < 4; i++) dst[i] = p[i];
            }
            __syncthreads();
            if (c < 7) {
                const uint4* src = (const uint4*)(hinh + (size_t)sr * H + (c + 1) * 128 + q * 32);
#pragma unroll
                for (int i = 0; i < 4; i++) p[i] = src[i];
            }
#pragma unroll
            for (int s = 0; s < 2; s++) {
                const int c0 = kg * 16 + s * 8;
                const int wc0 = c * 64 + kg * 16 + s * 8;
                uint32_t a[2][4], b[3][2];
#pragma unroll
                for (int ms = 0; ms < 2; ms++) {
                    int row = mg * 32 + ms * 16 + g;
                    a[ms][0] = Ab[row * A2S + c0 + tg];
                    a[ms][1] = Ab[(row + 8) * A2S + c0 + tg];
                    a[ms][2] = Ab[row * A2S + c0 + tg + 4];
                    a[ms][3] = Ab[(row + 8) * A2S + c0 + tg + 4];
                }
#pragma unroll
                for (int ns = 0; ns < 3; ns++) {
                    int br = ns * 8 + g;
                    b[ns][0] = Wsh[br * W2S + wc0 + tg];
                    b[ns][1] = Wsh[br * W2S + wc0 + tg + 4];
                }
#pragma unroll
                for (int ms = 0; ms < 2; ms++)
#pragma unroll
                    for (int ns = 0; ns < 3; ns++) mma_f16(acc[ms][ns], a[ms], b[ns]);
            }
        }
        __syncthreads();

#pragma unroll
        for (int ms = 0; ms < 2; ms++)
#pragma unroll
            for (int ns = 0; ns < 3; ns++)
#pragma unroll
                for (int i = 0; i < 4; i++) {
                    int row = mg * 32 + ms * 16 + g + (i >> 1) * 8;
                    int col = ns * 8 + 2 * tg + (i & 1);
                    Gsh[(kg * 64 + row) * G2S + col] = acc[ms][ns][i];
                }
        __syncthreads();

        {
            float aR = 0.f, aZ = 0.f, aN = 0.f;
#pragma unroll
            for (int k = 0; k < 4; k++) {
                const float* Gr = Gsh + (k * 64 + gb0) * G2S;
                aR += Gr[gu0]; aZ += Gr[8 + gu0]; aN += Gr[16 + gu0];
            }
            float rr = 1.0f / (1.0f + __expf(-(pR0 + aR + bR0)));
            float zz = 1.0f / (1.0f + __expf(-(pZ0 + aZ + bZ0)));
            float nn = tanhf(pN0 + cN0 + rr * (aN + bN0));
            float hn = (1.0f - zz) * nn + zz * hc0;
            int u = u0 + gu0;
            houtf[(size_t)gb0 * H + u] = hn;
            __half hh = __float2half_rn(hn);
            houth[(size_t)gb0 * H + u] = hh;
            if (DEC) st[(size_t)t * BATCH * H + (size_t)gb0 * H + u] = hh;
        }
        {
            float aR = 0.f, aZ = 0.f, aN = 0.f;
#pragma unroll
            for (int k = 0; k < 4; k++) {
                const float* Gr = Gsh + (k * 64 + gb1) * G2S;
                aR += Gr[gu1]; aZ += Gr[8 + gu1]; aN += Gr[16 + gu1];
            }
            float rr = 1.0f / (1.0f + __expf(-(pR1 + aR + bR1)));
            float zz = 1.0f / (1.0f + __expf(-(pZ1 + aZ + bZ1)));
            float nn = tanhf(pN1 + cN1 + rr * (aN + bN1));
            float hn = (1.0f - zz) * nn + zz * hc1;
            int u = u0 + gu1;
            houtf[(size_t)gb1 * H + u] = hn;
            __half hh = __float2half_rn(hn);
            houth[(size_t)gb1 * H + u] = hh;
            if (DEC) st[(size_t)t * BATCH * H + (size_t)gb1 * H + u] = hh;
        }

        __threadfence();
        __syncthreads();
        if (tid == 0) {
            unsigned old_gen = *(volatile unsigned*)&g_bar_gen;
            unsigned r = atomicAdd(&g_bar_cnt, 1);
            if (r == GRU_NCTA - 1) {
                atomicExch(&g_bar_cnt, 0);
                __threadfence();
                atomicAdd(&g_bar_gen, 1);
            } else {
                while (*(volatile unsigned*)&g_bar_gen == old_gen) {}
            }
        }
        __syncthreads();
    }
}

// ---------------- host orchestration ----------------
extern "C" void kernel_launch(void* const* d_in, const int* in_sizes, int n_in,
                              void* d_out, int out_size) {
    const int*   x        = (const int*)d_in[0];
    const int*   labels   = (const int*)d_in[1];
    const int*   bos      = (const int*)d_in[2];
    const float* enc_emb  = (const float*)d_in[3];
    const float* enc_Wih  = (const float*)d_in[4];
    const float* enc_Whh  = (const float*)d_in[5];
    const float* enc_bih  = (const float*)d_in[6];
    const float* enc_bhh  = (const float*)d_in[7];
    const float* dec_emb  = (const float*)d_in[8];
    const float* dec_Wih  = (const float*)d_in[9];
    const float* dec_Whh  = (const float*)d_in[10];
    const float* dec_bih  = (const float*)d_in[11];
    const float* dec_bhh  = (const float*)d_in[12];
    const float* dec_init = (const float*)d_in[13];
    const float* lin_W    = (const float*)d_in[14];
    const float* lin_b    = (const float*)d_in[15];
    float*       out      = (float*)d_out;

    __half *Xe, *Xw, *st, *We, *Wd, *Wl, *h0h, *h1h, *hd0h, *hd1h;
    float *Xi, *Xd, *ctx, *h0f, *h1f, *hd0f, *hd1f;
    cudaGetSymbolAddress((void**)&Xe, g_Xe);
    cudaGetSymbolAddress((void**)&Xi, g_Xi);
    cudaGetSymbolAddress((void**)&Xw, g_Xw);
    cudaGetSymbolAddress((void**)&Xd, g_Xd);
    cudaGetSymbolAddress((void**)&ctx, g_ctx);
    cudaGetSymbolAddress((void**)&h0f, g_h0f);
    cudaGetSymbolAddress((void**)&h1f, g_h1f);
    cudaGetSymbolAddress((void**)&h0h, g_h0h);
    cudaGetSymbolAddress((void**)&h1h, g_h1h);
    cudaGetSymbolAddress((void**)&hd0f, g_hd0f);
    cudaGetSymbolAddress((void**)&hd1f, g_hd1f);
    cudaGetSymbolAddress((void**)&hd0h, g_hd0h);
    cudaGetSymbolAddress((void**)&hd1h, g_hd1h);
    cudaGetSymbolAddress((void**)&st, g_st);
    cudaGetSymbolAddress((void**)&We, g_We);
    cudaGetSymbolAddress((void**)&Wd, g_Wd);
    cudaGetSymbolAddress((void**)&Wl, g_Wl);

    cudaFuncSetAttribute(gru_persistent_k<false>,
                         cudaFuncAttributeMaxDynamicSharedMemorySize, GRU_SMEM_BYTES);
    cudaFuncSetAttribute(gru_persistent_k<true>,
                         cudaFuncAttributeMaxDynamicSharedMemorySize, GRU_SMEM_BYTES);
    cudaFuncSetAttribute(gemm_f16_k,
                         cudaFuncAttributeMaxDynamicSharedMemorySize, GEMM_SMEM_BYTES);

    // ---- fp16 weight conversion ----
    conv_k<<<(3 * H * DEMB / 8 + 255) / 256, 256>>>(enc_Wih, We, 3 * H * DEMB / 8);
    conv_slice_k<<<3 * H, 128>>>(dec_Wih, Wd);
    conv_k<<<((size_t)VOCAB * H / 8 + 255) / 256, 256>>>(lin_W, Wl, VOCAB * H / 8);

    // ---- encoder ----
    embed_enc_k<<<TENC * BATCH, 128>>>(x, enc_emb, Xe);
    init_all_k<<<BATCH, H>>>(h0f, h0h, hd0f, hd0h, dec_init);
    gemm_f16_k<<<dim3(TENC * BATCH / 128, 3 * H / 256), 512, GEMM_SMEM_BYTES>>>(
        Xe, We, enc_bih, Xi, 3 * H, DEMB, 0);
    gru_persistent_k<false><<<GRU_NCTA, 256, GRU_SMEM_BYTES>>>(
        h0f, h1f, h0h, h1h, enc_Whh, enc_bhh, Xi, nullptr, nullptr, TENC);
    float* efin = h0f;   // TENC even -> final state in h0f

    // ---- decoder precompute ----
    embed_dec_k<<<TDEC * BATCH, 128>>>(labels, bos, dec_emb, Xw);
    gemm_f16_k<<<dim3(TDEC * BATCH / 128, 3 * H / 256), 512, GEMM_SMEM_BYTES>>>(
        Xw, Wd, dec_bih, Xd, 3 * H, DEMB, 0);
    gemm_tf32_k<<<dim3(1, 24), 256>>>(efin, H, dec_Wih, DEMB + H, DEMB, ctx,
                                      BATCH, 3 * H, H);
    gru_persistent_k<true><<<GRU_NCTA, 256, GRU_SMEM_BYTES>>>(
        hd0f, hd1f, hd0h, hd1h, dec_Whh, dec_bhh, Xd, ctx, st, TDEC);

    // ---- logits ----
    gemm_f16_k<<<dim3(TDEC * BATCH / 128, VOCAB / 256), 512, GEMM_SMEM_BYTES>>>(
        st, Wl, lin_b, out, VOCAB, H, 1);
}

// round 12
// speedup vs baseline: 1.2269x; 1.2269x over previous
#include <cuda_runtime.h>
#include <cuda_fp16.h>
#include <cstdint>
#include <math.h>

#define H     1024
#define BATCH 64
#define TENC  128
#define TDEC  64
#define VOCAB 32000
#define DEMB  512

// ---------------- persistent-GRU (128 CTAs x 8 units) smem layout ----------------
#define GRU_NCTA 128
#define W2S 516                       // half2 words per Whh row (512 + 4 pad)
#define A2S 68                        // half2 words per h-chunk row (64 + 4 pad)
#define G2S 28                        // fp32 per partial row (24 + 4 pad)
#define GRU_SMEM_WORDS (24 * W2S + 2 * 64 * A2S)
#define GRU_SMEM_BYTES (GRU_SMEM_WORDS * 4)

// ---------------- fp16 GEMM (Xi/Xd) smem: BM128 x BN256 x BK64, 3 stages ----------------
#define GSTG 49152                    // A 16KB + B 32KB
#define GEMM_SMEM_BYTES (3 * GSTG)    // 144KB, 1 CTA/SM

// ---------------- logits GEMM: A-only smem staging ----------------
#define LGS_STG 16384                 // A 128 rows x 128B
#define LGS_SMEM (3 * LGS_STG)        // 48KB
#define KC_LOG (H / 16)               // 64 k16-chunks

// ---------------- scratch ----------------
__device__ __half g_Xe[(size_t)TENC * BATCH * DEMB];
__device__ float  g_Xi[(size_t)TENC * BATCH * 3 * H];
__device__ __half g_Xw[(size_t)TDEC * BATCH * DEMB];
__device__ float  g_Xd[(size_t)TDEC * BATCH * 3 * H];
__device__ float  g_ctx[(size_t)BATCH * 3 * H];
__device__ float  g_h0f[(size_t)BATCH * H];
__device__ float  g_h1f[(size_t)BATCH * H];
__device__ __half g_h0h[(size_t)BATCH * H];
__device__ __half g_h1h[(size_t)BATCH * H];
__device__ float  g_hd0f[(size_t)BATCH * H];
__device__ float  g_hd1f[(size_t)BATCH * H];
__device__ __half g_hd0h[(size_t)BATCH * H];
__device__ __half g_hd1h[(size_t)BATCH * H];
__device__ __half g_st[(size_t)TDEC * BATCH * H];
__device__ __half g_We[(size_t)3 * H * DEMB];
__device__ __half g_Wd[(size_t)3 * H * DEMB];
__device__ __half g_Wl[(size_t)VOCAB * H];    // holds PERMUTED fragment-major lin_W
__device__ unsigned g_bar_cnt;
__device__ unsigned g_bar_gen;

// ---------------- helpers ----------------
__device__ __forceinline__ uint32_t pack2(float x, float y) {
    __half2 h = __floats2half2_rn(x, y);
    return *(uint32_t*)&h;
}
__device__ __forceinline__ uint32_t f2tf32(float f) {
    uint32_t r;
    asm("cvt.rna.tf32.f32 %0, %1;" : "=r"(r) : "f"(f));
    return r;
}
__device__ __forceinline__ void cvt_store4(uint32_t* dst, float4 v) {
    dst[0] = f2tf32(v.x); dst[1] = f2tf32(v.y);
    dst[2] = f2tf32(v.z); dst[3] = f2tf32(v.w);
}
__device__ __forceinline__ void mma_f16(float* c, const uint32_t* a, const uint32_t* b) {
    asm volatile(
        "mma.sync.aligned.m16n8k16.row.col.f32.f16.f16.f32 "
        "{%0,%1,%2,%3}, {%4,%5,%6,%7}, {%8,%9}, {%0,%1,%2,%3};\n"
        : "+f"(c[0]), "+f"(c[1]), "+f"(c[2]), "+f"(c[3])
        : "r"(a[0]), "r"(a[1]), "r"(a[2]), "r"(a[3]), "r"(b[0]), "r"(b[1]));
}
__device__ __forceinline__ void mma_tf32(float* c, const uint32_t* a, const uint32_t* b) {
    asm volatile(
        "mma.sync.aligned.m16n8k8.row.col.f32.tf32.tf32.f32 "
        "{%0,%1,%2,%3}, {%4,%5,%6,%7}, {%8,%9}, {%0,%1,%2,%3};\n"
        : "+f"(c[0]), "+f"(c[1]), "+f"(c[2]), "+f"(c[3])
        : "r"(a[0]), "r"(a[1]), "r"(a[2]), "r"(a[3]), "r"(b[0]), "r"(b[1]));
}
__device__ __forceinline__ uint32_t smem_u32(const void* p) {
    uint32_t a;
    asm("{ .reg .u64 t; cvta.to.shared.u64 t, %1; cvt.u32.u64 %0, t; }" : "=r"(a) : "l"(p));
    return a;
}
__device__ __forceinline__ uint32_t swz128(uint32_t o) { return o ^ ((o >> 3) & 0x70); }
__device__ __forceinline__ void cp16(uint32_t dst, const void* src) {
    asm volatile("cp.async.cg.shared.global [%0], [%1], 16;\n" :: "r"(dst), "l"(src) : "memory");
}
#define LDSM4(r0, r1, r2, r3, addr) \
    asm volatile("ldmatrix.sync.aligned.m8n8.x4.shared.b16 {%0,%1,%2,%3}, [%4];" \
                 : "=r"(r0), "=r"(r1), "=r"(r2), "=r"(r3) : "r"(addr))

// ---------------- weight fp16 conversion ----------------
__global__ void conv_k(const float* __restrict__ src, __half* __restrict__ dst, int n8) {
    int i = blockIdx.x * 256 + threadIdx.x;
    if (i < n8) {
        float4 a = ((const float4*)src)[2 * i];
        float4 b = ((const float4*)src)[2 * i + 1];
        uint4 u;
        u.x = pack2(a.x, a.y); u.y = pack2(a.z, a.w);
        u.z = pack2(b.x, b.y); u.w = pack2(b.z, b.w);
        ((uint4*)dst)[i] = u;
    }
}
__global__ void conv_slice_k(const float* __restrict__ src, __half* __restrict__ dst) {
    int r = blockIdx.x;
    float4 v = ((const float4*)(src + (size_t)r * (DEMB + H)))[threadIdx.x];
    uint2 u; u.x = pack2(v.x, v.y); u.y = pack2(v.z, v.w);
    ((uint2*)(dst + (size_t)r * DEMB))[threadIdx.x] = u;
}

// ---------------- lin_W fragment-major permute (fp32 -> fp16) ----------------
// Output uint4 per (nbg, kcg, lane): thread's mma B-operand words for the
// 16-row n-group nbg, k16-chunk kcg:
//   x = W[nbg*16 + (l>>2)][kcg*16 + (l&3)*2 .. +1]
//   y = same cols, row +8 ; z = cols +8, row base ; w = cols +8, row +8
__global__ void permute_wl_k(const float* __restrict__ W, uint4* __restrict__ Bp) {
    int w = (blockIdx.x * blockDim.x + threadIdx.x) >> 5;
    int lane = threadIdx.x & 31;
    int nbg = w >> 6, kcg = w & 63;            // VOCAB/16=2000 nbg, 64 kcg
    int row0 = nbg * 16 + (lane >> 2);
    int col0 = kcg * 16 + (lane & 3) * 2;
    const float* p00 = W + (size_t)row0 * H + col0;
    const float* p10 = W + (size_t)(row0 + 8) * H + col0;
    float2 v00 = *(const float2*)(p00);
    float2 v10 = *(const float2*)(p10);
    float2 v01 = *(const float2*)(p00 + 8);
    float2 v11 = *(const float2*)(p10 + 8);
    uint4 o;
    o.x = pack2(v00.x, v00.y);
    o.y = pack2(v10.x, v10.y);
    o.z = pack2(v01.x, v01.y);
    o.w = pack2(v11.x, v11.y);
    Bp[(size_t)w * 32 + lane] = o;
}

// ---------------- embedding gathers -> fp16 ----------------
__global__ void embed_enc_k(const int* __restrict__ x, const float* __restrict__ emb,
                            __half* __restrict__ Xe) {
    int row = blockIdx.x;
    int t = row >> 6, b = row & 63;
    int tok = x[b * TENC + t];
    float4 v = ((const float4*)(emb + (size_t)tok * DEMB))[threadIdx.x];
    uint2 u; u.x = pack2(v.x, v.y); u.y = pack2(v.z, v.w);
    ((uint2*)(Xe + (size_t)row * DEMB))[threadIdx.x] = u;
}
__global__ void embed_dec_k(const int* __restrict__ labels, const int* __restrict__ bos,
                            const float* __restrict__ emb, __half* __restrict__ Xw) {
    int row = blockIdx.x;
    int t = row >> 6, b = row & 63;
    int tok = (t == 0) ? bos[0] : labels[b * TDEC + t - 1];
    float4 v = ((const float4*)(emb + (size_t)tok * DEMB))[threadIdx.x];
    uint2 u; u.x = pack2(v.x, v.y); u.y = pack2(v.z, v.w);
    ((uint2*)(Xw + (size_t)row * DEMB))[threadIdx.x] = u;
}

__global__ void init_all_k(float* __restrict__ h0f, __half* __restrict__ h0h,
                           float* __restrict__ hd0f, __half* __restrict__ hd0h,
                           const float* __restrict__ dec_init) {
    int b = blockIdx.x, u = threadIdx.x;
    h0f[b * H + u] = 0.0f;
    h0h[b * H + u] = __float2half_rn(0.0f);
    float di = dec_init[u];
    hd0f[b * H + u] = di;
    hd0h[b * H + u] = __float2half_rn(di);
    if (b == 0 && u == 0) { g_bar_cnt = 0; g_bar_gen = 0; }
}

// ---------------- fp16 GEMM (Xi/Xd): C = A @ B^T + bias  (round-10 proven path) ----------------
__global__ __launch_bounds__(512, 1)
void gemm_f16_k(const __half* __restrict__ A, const __half* __restrict__ B,
                const float* __restrict__ bias, float* __restrict__ C,
                int N, int K) {
    extern __shared__ char smc[];
    const uint32_t sb = smem_u32(smc);
    const int m0 = blockIdx.x * 128, n0 = blockIdx.y * 256;
    const int tid = threadIdx.x, lane = tid & 31, wid = tid >> 5;
    const int wr = wid >> 2, wc = wid & 3;
    const int g = lane >> 2, tg = lane & 3;

    float acc[2][8][4];
#pragma unroll
    for (int ms = 0; ms < 2; ms++)
#pragma unroll
        for (int ns = 0; ns < 8; ns++)
#pragma unroll
            for (int i = 0; i < 4; i++) acc[ms][ns][i] = 0.0f;

    const __half* Ab = A + (size_t)m0 * K;
    const __half* Bb = B + (size_t)n0 * K;

    auto load_stage = [&](int s, int k0) {
        uint32_t sbase = sb + s * GSTG;
#pragma unroll
        for (int i = 0; i < 2; i++) {
            int idx = tid + i * 512;
            int row = idx >> 3, c = idx & 7;
            cp16(sbase + swz128(row * 128 + c * 16), Ab + (size_t)row * K + k0 + c * 8);
        }
#pragma unroll
        for (int i = 0; i < 4; i++) {
            int idx = tid + i * 512;
            int row = idx >> 3, c = idx & 7;
            cp16(sbase + 16384 + swz128(row * 128 + c * 16), Bb + (size_t)row * K + k0 + c * 8);
        }
        asm volatile("cp.async.commit_group;\n" ::: "memory");
    };

    const int NT = K >> 6;
    load_stage(0, 0);
    load_stage(1, 64);

    const int r16 = lane & 15, chb = (lane >> 4) << 4;

    for (int it = 0; it < NT; ++it) {
        const int s = it % 3;
        if (it == NT - 1) asm volatile("cp.async.wait_group 0;\n" ::: "memory");
        else              asm volatile("cp.async.wait_group 1;\n" ::: "memory");
        __syncthreads();
        if (it + 2 < NT) load_stage((it + 2) % 3, (it + 2) * 64);

        const uint32_t sA = sb + s * GSTG;
        const uint32_t sB = sA + 16384;
#pragma unroll
        for (int kk = 0; kk < 4; kk++) {
            const int kb = kk * 32 + chb;
            uint32_t a[2][4], b[8][2];
#pragma unroll
            for (int ms = 0; ms < 2; ms++) {
                uint32_t ad = sA + swz128(((wr * 32 + ms * 16 + r16) << 7) + kb);
                LDSM4(a[ms][0], a[ms][1], a[ms][2], a[ms][3], ad);
            }
#pragma unroll
            for (int np = 0; np < 4; np++) {
                uint32_t bd = sB + swz128(((wc * 64 + np * 16 + r16) << 7) + kb);
                uint32_t r0, r1, r2, r3;
                LDSM4(r0, r1, r2, r3, bd);
                b[2 * np][0] = r0; b[2 * np + 1][0] = r1;
                b[2 * np][1] = r2; b[2 * np + 1][1] = r3;
            }
#pragma unroll
            for (int ms = 0; ms < 2; ms++)
#pragma unroll
                for (int ns = 0; ns < 8; ns++)
                    mma_f16(acc[ms][ns], a[ms], b[ns]);
        }
        __syncthreads();
    }

#pragma unroll
    for (int ms = 0; ms < 2; ms++)
#pragma unroll
        for (int ns = 0; ns < 8; ns++) {
            int row = m0 + wr * 32 + ms * 16 + g;
            int col = n0 + wc * 64 + ns * 8 + 2 * tg;
            float b0 = bias[col], b1 = bias[col + 1];
#pragma unroll
            for (int h2 = 0; h2 < 2; h2++) {
                int r = row + h2 * 8;
                size_t idx = (size_t)r * (size_t)N + col;
                float2 v;
                v.x = acc[ms][ns][h2 * 2 + 0] + b0;
                v.y = acc[ms][ns][h2 * 2 + 1] + b1;
                *(float2*)(C + idx) = v;
            }
        }
}

// ---------------- logits GEMM: B direct-from-gmem (fragment-major), A via smem ----------------
// BM=128, BN=256, BK=64, K=1024 fixed. 512 threads: wr=wid>>3 (m, 2x64), wc=wid&7 (n, 8x32).
// Output transposed: rows (t*BATCH+b) -> out[b][t][v].
__global__ __launch_bounds__(512, 1)
void gemm_logits_k(const __half* __restrict__ A, const uint4* __restrict__ Bp,
                   const float* __restrict__ bias, float* __restrict__ C) {
    extern __shared__ char smc[];
    const uint32_t sb = smem_u32(smc);
    const int m0 = blockIdx.x * 128, n0 = blockIdx.y * 256;
    const int tid = threadIdx.x, lane = tid & 31, wid = tid >> 5;
    const int wr = wid >> 3, wc = wid & 7;
    const int g = lane >> 2, tg = lane & 3;

    float acc[4][4][4];
#pragma unroll
    for (int ms = 0; ms < 4; ms++)
#pragma unroll
        for (int j = 0; j < 4; j++)
#pragma unroll
            for (int i = 0; i < 4; i++) acc[ms][j][i] = 0.0f;

    const __half* Ab = A + (size_t)m0 * H;
    const int nbg0 = (n0 + wc * 32) >> 4;
    const uint4* Bp0 = Bp + ((size_t)nbg0 * KC_LOG) * 32 + lane;
    const uint4* Bp1 = Bp + ((size_t)(nbg0 + 1) * KC_LOG) * 32 + lane;

    auto load_stageA = [&](int s, int k0) {
        uint32_t sbase = sb + s * LGS_STG;
#pragma unroll
        for (int i = 0; i < 2; i++) {
            int idx = tid + i * 512;
            int row = idx >> 3, c = idx & 7;
            cp16(sbase + swz128(row * 128 + c * 16), Ab + (size_t)row * H + k0 + c * 8);
        }
        asm volatile("cp.async.commit_group;\n" ::: "memory");
    };

    const int NT = H >> 6;   // 16
    load_stageA(0, 0);
    load_stageA(1, 64);

    const int r16 = lane & 15, chb = (lane >> 4) << 4;

    for (int it = 0; it < NT; ++it) {
        const int s = it % 3;
        const int kcg0 = it * 4;
        // issue this iter's first B loads before waiting on A (independent of smem)
        uint4 bv0 = Bp0[(size_t)kcg0 * 32];
        uint4 bv1 = Bp1[(size_t)kcg0 * 32];

        if (it == NT - 1) asm volatile("cp.async.wait_group 0;\n" ::: "memory");
        else              asm volatile("cp.async.wait_group 1;\n" ::: "memory");
        __syncthreads();
        if (it + 2 < NT) load_stageA((it + 2) % 3, (it + 2) * 64);

        const uint32_t sA = sb + s * LGS_STG;
#pragma unroll
        for (int kc = 0; kc < 4; kc++) {
            uint4 cb0 = bv0, cb1 = bv1;
            if (kc < 3) {
                bv0 = Bp0[(size_t)(kcg0 + kc + 1) * 32];
                bv1 = Bp1[(size_t)(kcg0 + kc + 1) * 32];
            }
            const int kb = kc * 32 + chb;
            uint32_t a[4][4];
#pragma unroll
            for (int ms = 0; ms < 4; ms++) {
                uint32_t ad = sA + swz128(((wr * 64 + ms * 16 + r16) << 7) + kb);
                LDSM4(a[ms][0], a[ms][1], a[ms][2], a[ms][3], ad);
            }
            uint32_t b[4][2];
            b[0][0] = cb0.x; b[0][1] = cb0.z;
            b[1][0] = cb0.y; b[1][1] = cb0.w;
            b[2][0] = cb1.x; b[2][1] = cb1.z;
            b[3][0] = cb1.y; b[3][1] = cb1.w;
#pragma unroll
            for (int ms = 0; ms < 4; ms++)
#pragma unroll
                for (int j = 0; j < 4; j++)
                    mma_f16(acc[ms][j], a[ms], b[j]);
        }
        __syncthreads();
    }

#pragma unroll
    for (int ms = 0; ms < 4; ms++)
#pragma unroll
        for (int j = 0; j < 4; j++) {
            int row = m0 + wr * 64 + ms * 16 + g;
            int col = n0 + wc * 32 + j * 8 + 2 * tg;
            float b0 = bias[col], b1 = bias[col + 1];
#pragma unroll
            for (int h2 = 0; h2 < 2; h2++) {
                int r = row + h2 * 8;
                int bb = r & 63, tt = r >> 6;
                size_t idx = ((size_t)bb * TDEC + tt) * (size_t)VOCAB + col;
                float2 v;
                v.x = acc[ms][j][h2 * 2 + 0] + b0;
                v.y = acc[ms][j][h2 * 2 + 1] + b1;
                *(float2*)(C + idx) = v;
            }
        }
}

// ---------------- small tf32 GEMM (ctx only: 64 x 3072 x 1024) ----------------
__global__ __launch_bounds__(256, 2)
void gemm_tf32_k(const float* __restrict__ A, int lda,
                 const float* __restrict__ W, int ldw, int koff,
                 float* __restrict__ C, int M, int N, int K) {
    __shared__ uint32_t As[128][20];
    __shared__ uint32_t Bs[128][20];
    const int m0 = blockIdx.x * 128, n0 = blockIdx.y * 128;
    const int tid = threadIdx.x, lane = tid & 31, wid = tid >> 5;
    const int wr = wid >> 1, wc = wid & 1;
    const int g = lane >> 2, tg = lane & 3;
    float acc[2][8][4];
#pragma unroll
    for (int ms = 0; ms < 2; ms++)
#pragma unroll
        for (int ns = 0; ns < 8; ns++)
#pragma unroll
            for (int i = 0; i < 4; i++) acc[ms][ns][i] = 0.0f;
    const int lrow = tid >> 1, lcol = (tid & 1) * 8;
    const float* Ap = A + (size_t)(m0 + lrow) * lda + lcol;
    const float* Wp = W + (size_t)(n0 + lrow) * ldw + koff + lcol;
    const bool aok = (m0 + lrow) < M;
    for (int k0 = 0; k0 < K; k0 += 16) {
        if (aok) {
            cvt_store4(&As[lrow][lcol], *(const float4*)(Ap + k0));
            cvt_store4(&As[lrow][lcol + 4], *(const float4*)(Ap + k0 + 4));
        } else {
#pragma unroll
            for (int i = 0; i < 8; i++) As[lrow][lcol + i] = 0u;
        }
        cvt_store4(&Bs[lrow][lcol], *(const float4*)(Wp + k0));
        cvt_store4(&Bs[lrow][lcol + 4], *(const float4*)(Wp + k0 + 4));
        __syncthreads();
#pragma unroll
        for (int kk = 0; kk < 16; kk += 8) {
            uint32_t a[2][4], b[8][2];
#pragma unroll
            for (int ms = 0; ms < 2; ms++) {
                int r0 = wr * 32 + ms * 16 + g;
                a[ms][0] = As[r0][kk + tg]; a[ms][1] = As[r0 + 8][kk + tg];
                a[ms][2] = As[r0][kk + tg + 4]; a[ms][3] = As[r0 + 8][kk + tg + 4];
            }
#pragma unroll
            for (int ns = 0; ns < 8; ns++) {
                int br = wc * 64 + ns * 8 + g;
                b[ns][0] = Bs[br][kk + tg]; b[ns][1] = Bs[br][kk + tg + 4];
            }
#pragma unroll
            for (int ms = 0; ms < 2; ms++)
#pragma unroll
                for (int ns = 0; ns < 8; ns++) mma_tf32(acc[ms][ns], a[ms], b[ns]);
        }
        __syncthreads();
    }
#pragma unroll
    for (int ms = 0; ms < 2; ms++)
#pragma unroll
        for (int ns = 0; ns < 8; ns++) {
            int row = m0 + wr * 32 + ms * 16 + g;
            int col = n0 + wc * 64 + ns * 8 + 2 * tg;
#pragma unroll
            for (int h2 = 0; h2 < 2; h2++) {
                int r = row + h2 * 8;
                if (r < M) {
                    size_t idx = (size_t)r * (size_t)N + col;
                    float2 v;
                    v.x = acc[ms][ns][h2 * 2 + 0];
                    v.y = acc[ms][ns][h2 * 2 + 1];
                    *(float2*)(C + idx) = v;
                }
            }
        }
}

// ---------------- persistent GRU recurrence: 128 CTAs x 8 hidden units ----------------
// ctx_r/ctx_z fold into sigmoid biases; ctx_n stays OUTSIDE the r*() product.
template <bool DEC>
__global__ __launch_bounds__(256, 1)
void gru_persistent_k(float* __restrict__ h0f, float* __restrict__ h1f,
                      __half* __restrict__ h0h, __half* __restrict__ h1h,
                      const float* __restrict__ Whh, const float* __restrict__ bhh,
                      const float* __restrict__ gi, const float* __restrict__ ctx,
                      __half* __restrict__ st, int T) {
    extern __shared__ uint32_t sm[];
    uint32_t* Wsh = sm;
    uint32_t* Ash = sm + 24 * W2S;
    float* Gsh = (float*)(sm + 24 * W2S);

    const int u0 = blockIdx.x * 8;
    const int tid = threadIdx.x, lane = tid & 31, wid = tid >> 5;
    const int kg = wid >> 1, mg = wid & 1;
    const int g = lane >> 2, tg = lane & 3;

    for (int j = 0; j < 24; j++) {
        int grow = (j >> 3) * H + u0 + (j & 7);
        float4 v = *(const float4*)(Whh + (size_t)grow * H + tid * 4);
        Wsh[j * W2S + tid * 2]     = pack2(v.x, v.y);
        Wsh[j * W2S + tid * 2 + 1] = pack2(v.z, v.w);
    }
    const int sr = tid >> 2, q = tid & 3;
    const int gb0 = tid >> 3, gu0 = tid & 7;
    const int gb1 = (tid + 256) >> 3, gu1 = (tid + 256) & 7;

    float bR0 = bhh[u0 + gu0], bZ0 = bhh[H + u0 + gu0], bN0 = bhh[2 * H + u0 + gu0];
    float bR1 = bhh[u0 + gu1], bZ1 = bhh[H + u0 + gu1], bN1 = bhh[2 * H + u0 + gu1];
    float cN0 = 0.0f, cN1 = 0.0f;
    if (DEC) {
        bR0 += ctx[(size_t)gb0 * 3 * H + u0 + gu0];
        bZ0 += ctx[(size_t)gb0 * 3 * H + H + u0 + gu0];
        cN0  = ctx[(size_t)gb0 * 3 * H + 2 * H + u0 + gu0];
        bR1 += ctx[(size_t)gb1 * 3 * H + u0 + gu1];
        bZ1 += ctx[(size_t)gb1 * 3 * H + H + u0 + gu1];
        cN1  = ctx[(size_t)gb1 * 3 * H + 2 * H + u0 + gu1];
    }

    for (int t = 0; t < T; t++) {
        const float* hinf = (t & 1) ? h1f : h0f;
        const __half* hinh = (t & 1) ? h1h : h0h;
        float* houtf = (t & 1) ? h0f : h1f;
        __half* houth = (t & 1) ? h0h : h1h;
        const float* gi_t = gi + (size_t)t * BATCH * 3 * H;

        float pR0 = gi_t[(size_t)gb0 * 3 * H + u0 + gu0];
        float pZ0 = gi_t[(size_t)gb0 * 3 * H + H + u0 + gu0];
        float pN0 = gi_t[(size_t)gb0 * 3 * H + 2 * H + u0 + gu0];
        float pR1 = gi_t[(size_t)gb1 * 3 * H + u0 + gu1];
        float pZ1 = gi_t[(size_t)gb1 * 3 * H + H + u0 + gu1];
        float pN1 = gi_t[(size_t)gb1 * 3 * H + 2 * H + u0 + gu1];
        float hc0 = hinf[(size_t)gb0 * H + u0 + gu0];
        float hc1 = hinf[(size_t)gb1 * H + u0 + gu1];

        uint4 p[4];
        {
            const uint4* src = (const uint4*)(hinh + (size_t)sr * H + q * 32);
#pragma unroll
            for (int i = 0; i < 4; i++) p[i] = src[i];
        }

        float acc[2][3][4];
#pragma unroll
        for (int ms = 0; ms < 2; ms++)
#pragma unroll
            for (int ns = 0; ns < 3; ns++)
#pragma unroll
                for (int i = 0; i < 4; i++) acc[ms][ns][i] = 0.0f;

        for (int c = 0; c < 8; c++) {
            uint32_t* Ab = Ash + (c & 1) * 64 * A2S;
            {
                uint4* dst = (uint4*)(Ab + sr * A2S + q * 16);
#pragma unroll
                for (int i = 0; i < 4; i++) dst[i] = p[i];
            }
            __syncthreads();
            if (c < 7) {
                const uint4* src = (const uint4*)(hinh + (size_t)sr * H + (c + 1) * 128 + q * 32);
#pragma unroll
                for (int i = 0; i < 4; i++) p[i] = src[i];
            }
#pragma unroll
            for (int s = 0; s < 2; s++) {
                const int c0 = kg * 16 + s * 8;
                const int wc0 = c * 64 + kg * 16 + s * 8;
                uint32_t a[2][4], b[3][2];
#pragma unroll
                for (int ms = 0; ms < 2; ms++) {
                    int row = mg * 32 + ms * 16 + g;
                    a[ms][0] = Ab[row * A2S + c0 + tg];
                    a[ms][1] = Ab[(row + 8) * A2S + c0 + tg];
                    a[ms][2] = Ab[row * A2S + c0 + tg + 4];
                    a[ms][3] = Ab[(row + 8) * A2S + c0 + tg + 4];
                }
#pragma unroll
                for (int ns = 0; ns < 3; ns++) {
                    int br = ns * 8 + g;
                    b[ns][0] = Wsh[br * W2S + wc0 + tg];
                    b[ns][1] = Wsh[br * W2S + wc0 + tg + 4];
                }
#pragma unroll
                for (int ms = 0; ms < 2; ms++)
#pragma unroll
                    for (int ns = 0; ns < 3; ns++) mma_f16(acc[ms][ns], a[ms], b[ns]);
            }
        }
        __syncthreads();

#pragma unroll
        for (int ms = 0; ms < 2; ms++)
#pragma unroll
            for (int ns = 0; ns < 3; ns++)
#pragma unroll
                for (int i = 0; i < 4; i++) {
                    int row = mg * 32 + ms * 16 + g + (i >> 1) * 8;
                    int col = ns * 8 + 2 * tg + (i & 1);
                    Gsh[(kg * 64 + row) * G2S + col] = acc[ms][ns][i];
                }
        __syncthreads();

        {
            float aR = 0.f, aZ = 0.f, aN = 0.f;
#pragma unroll
            for (int k = 0; k < 4; k++) {
                const float* Gr = Gsh + (k * 64 + gb0) * G2S;
                aR += Gr[gu0]; aZ += Gr[8 + gu0]; aN += Gr[16 + gu0];
            }
            float rr = 1.0f / (1.0f + __expf(-(pR0 + aR + bR0)));
            float zz = 1.0f / (1.0f + __expf(-(pZ0 + aZ + bZ0)));
            float nn = tanhf(pN0 + cN0 + rr * (aN + bN0));
            float hn = (1.0f - zz) * nn + zz * hc0;
            int u = u0 + gu0;
            houtf[(size_t)gb0 * H + u] = hn;
            __half hh = __float2half_rn(hn);
            houth[(size_t)gb0 * H + u] = hh;
            if (DEC) st[(size_t)t * BATCH * H + (size_t)gb0 * H + u] = hh;
        }
        {
            float aR = 0.f, aZ = 0.f, aN = 0.f;
#pragma unroll
            for (int k = 0; k < 4; k++) {
                const float* Gr = Gsh + (k * 64 + gb1) * G2S;
                aR += Gr[gu1]; aZ += Gr[8 + gu1]; aN += Gr[16 + gu1];
            }
            float rr = 1.0f / (1.0f + __expf(-(pR1 + aR + bR1)));
            float zz = 1.0f / (1.0f + __expf(-(pZ1 + aZ + bZ1)));
            float nn = tanhf(pN1 + cN1 + rr * (aN + bN1));
            float hn = (1.0f - zz) * nn + zz * hc1;
            int u = u0 + gu1;
            houtf[(size_t)gb1 * H + u] = hn;
            __half hh = __float2half_rn(hn);
            houth[(size_t)gb1 * H + u] = hh;
            if (DEC) st[(size_t)t * BATCH * H + (size_t)gb1 * H + u] = hh;
        }

        __threadfence();
        __syncthreads();
        if (tid == 0) {
            unsigned old_gen = *(volatile unsigned*)&g_bar_gen;
            unsigned r = atomicAdd(&g_bar_cnt, 1);
            if (r == GRU_NCTA - 1) {
                atomicExch(&g_bar_cnt, 0);
                __threadfence();
                atomicAdd(&g_bar_gen, 1);
            } else {
                while (*(volatile unsigned*)&g_bar_gen == old_gen) {}
            }
        }
        __syncthreads();
    }
}

// ---------------- host orchestration ----------------
extern "C" void kernel_launch(void* const* d_in, const int* in_sizes, int n_in,
                              void* d_out, int out_size) {
    const int*   x        = (const int*)d_in[0];
    const int*   labels   = (const int*)d_in[1];
    const int*   bos      = (const int*)d_in[2];
    const float* enc_emb  = (const float*)d_in[3];
    const float* enc_Wih  = (const float*)d_in[4];
    const float* enc_Whh  = (const float*)d_in[5];
    const float* enc_bih  = (const float*)d_in[6];
    const float* enc_bhh  = (const float*)d_in[7];
    const float* dec_emb  = (const float*)d_in[8];
    const float* dec_Wih  = (const float*)d_in[9];
    const float* dec_Whh  = (const float*)d_in[10];
    const float* dec_bih  = (const float*)d_in[11];
    const float* dec_bhh  = (const float*)d_in[12];
    const float* dec_init = (const float*)d_in[13];
    const float* lin_W    = (const float*)d_in[14];
    const float* lin_b    = (const float*)d_in[15];
    float*       out      = (float*)d_out;

    __half *Xe, *Xw, *st, *We, *Wd, *Wl, *h0h, *h1h, *hd0h, *hd1h;
    float *Xi, *Xd, *ctx, *h0f, *h1f, *hd0f, *hd1f;
    cudaGetSymbolAddress((void**)&Xe, g_Xe);
    cudaGetSymbolAddress((void**)&Xi, g_Xi);
    cudaGetSymbolAddress((void**)&Xw, g_Xw);
    cudaGetSymbolAddress((void**)&Xd, g_Xd);
    cudaGetSymbolAddress((void**)&ctx, g_ctx);
    cudaGetSymbolAddress((void**)&h0f, g_h0f);
    cudaGetSymbolAddress((void**)&h1f, g_h1f);
    cudaGetSymbolAddress((void**)&h0h, g_h0h);
    cudaGetSymbolAddress((void**)&h1h, g_h1h);
    cudaGetSymbolAddress((void**)&hd0f, g_hd0f);
    cudaGetSymbolAddress((void**)&hd1f, g_hd1f);
    cudaGetSymbolAddress((void**)&hd0h, g_hd0h);
    cudaGetSymbolAddress((void**)&hd1h, g_hd1h);
    cudaGetSymbolAddress((void**)&st, g_st);
    cudaGetSymbolAddress((void**)&We, g_We);
    cudaGetSymbolAddress((void**)&Wd, g_Wd);
    cudaGetSymbolAddress((void**)&Wl, g_Wl);

    cudaFuncSetAttribute(gru_persistent_k<false>,
                         cudaFuncAttributeMaxDynamicSharedMemorySize, GRU_SMEM_BYTES);
    cudaFuncSetAttribute(gru_persistent_k<true>,
                         cudaFuncAttributeMaxDynamicSharedMemorySize, GRU_SMEM_BYTES);
    cudaFuncSetAttribute(gemm_f16_k,
                         cudaFuncAttributeMaxDynamicSharedMemorySize, GEMM_SMEM_BYTES);
    cudaFuncSetAttribute(gemm_logits_k,
                         cudaFuncAttributeMaxDynamicSharedMemorySize, LGS_SMEM);

    // ---- weight prep ----
    conv_k<<<(3 * H * DEMB / 8 + 255) / 256, 256>>>(enc_Wih, We, 3 * H * DEMB / 8);
    conv_slice_k<<<3 * H, 128>>>(dec_Wih, Wd);
    permute_wl_k<<<(VOCAB / 16) * KC_LOG / 8, 256>>>(lin_W, (uint4*)Wl);

    // ---- encoder ----
    embed_enc_k<<<TENC * BATCH, 128>>>(x, enc_emb, Xe);
    init_all_k<<<BATCH, H>>>(h0f, h0h, hd0f, hd0h, dec_init);
    gemm_f16_k<<<dim3(TENC * BATCH / 128, 3 * H / 256), 512, GEMM_SMEM_BYTES>>>(
        Xe, We, enc_bih, Xi, 3 * H, DEMB);
    gru_persistent_k<false><<<GRU_NCTA, 256, GRU_SMEM_BYTES>>>(
        h0f, h1f, h0h, h1h, enc_Whh, enc_bhh, Xi, nullptr, nullptr, TENC);
    float* efin = h0f;   // TENC even -> final state in h0f

    // ---- decoder precompute ----
    embed_dec_k<<<TDEC * BATCH, 128>>>(labels, bos, dec_emb, Xw);
    gemm_f16_k<<<dim3(TDEC * BATCH / 128, 3 * H / 256), 512, GEMM_SMEM_BYTES>>>(
        Xw, Wd, dec_bih, Xd, 3 * H, DEMB);
    gemm_tf32_k<<<dim3(1, 24), 256>>>(efin, H, dec_Wih, DEMB + H, DEMB, ctx,
                                      BATCH, 3 * H, H);
    gru_persistent_k<true><<<GRU_NCTA, 256, GRU_SMEM_BYTES>>>(
        hd0f, hd1f, hd0h, hd1h, dec_Whh, dec_bhh, Xd, ctx, st, TDEC);

    // ---- logits ----
    gemm_logits_k<<<dim3(TDEC * BATCH / 128, VOCAB / 256), 512, LGS_SMEM>>>(
        st, (const uint4*)Wl, lin_b, out);
}

// round 13
// speedup vs baseline: 1.3076x; 1.0658x over previous
#include <cuda_runtime.h>
#include <cuda_fp16.h>
#include <cstdint>
#include <math.h>

#define H     1024
#define BATCH 64
#define TENC  128
#define TDEC  64
#define VOCAB 32000
#define DEMB  512

// ---------------- persistent-GRU (128 CTAs x 8 units) smem layout ----------------
#define GRU_NCTA 128
#define W2S 516
#define A2S 68
#define G2S 28
#define GRU_SMEM_WORDS (24 * W2S + 2 * 64 * A2S)
#define GRU_SMEM_BYTES (GRU_SMEM_WORDS * 4)

// ---------------- fp16 GEMM (Xi/Xd) smem: BM128 x BN256 x BK64, 3 stages ----------------
#define GSTG 49152
#define GEMM_SMEM_BYTES (3 * GSTG)

// ---------------- logits GEMM: A cp.async (16KB) + B bulk (32KB) per stage ----------------
#define LG_ASTG 16384
#define LG_BSTG 32768
#define LG_STG  (LG_ASTG + LG_BSTG)      // 48KB
#define LG_SMEM (3 * LG_STG + 64)        // + mbarriers
#define KC_LOG (H / 16)                  // 64 k16-chunks

// ---------------- scratch ----------------
__device__ __half g_Xe[(size_t)TENC * BATCH * DEMB];
__device__ float  g_Xi[(size_t)TENC * BATCH * 3 * H];
__device__ __half g_Xw[(size_t)TDEC * BATCH * DEMB];
__device__ float  g_Xd[(size_t)TDEC * BATCH * 3 * H];
__device__ float  g_ctx[(size_t)BATCH * 3 * H];
__device__ float  g_h0f[(size_t)BATCH * H];
__device__ float  g_h1f[(size_t)BATCH * H];
__device__ __half g_h0h[(size_t)BATCH * H];
__device__ __half g_h1h[(size_t)BATCH * H];
__device__ float  g_hd0f[(size_t)BATCH * H];
__device__ float  g_hd1f[(size_t)BATCH * H];
__device__ __half g_hd0h[(size_t)BATCH * H];
__device__ __half g_hd1h[(size_t)BATCH * H];
__device__ __half g_st[(size_t)TDEC * BATCH * H];
__device__ __half g_We[(size_t)3 * H * DEMB];
__device__ __half g_Wd[(size_t)3 * H * DEMB];
__device__ __half g_Wl[(size_t)VOCAB * H];    // PERMUTED fragment-major lin_W
__device__ unsigned g_bar_cnt;
__device__ unsigned g_bar_gen;

// ---------------- helpers ----------------
__device__ __forceinline__ uint32_t pack2(float x, float y) {
    __half2 h = __floats2half2_rn(x, y);
    return *(uint32_t*)&h;
}
__device__ __forceinline__ uint32_t f2tf32(float f) {
    uint32_t r;
    asm("cvt.rna.tf32.f32 %0, %1;" : "=r"(r) : "f"(f));
    return r;
}
__device__ __forceinline__ void cvt_store4(uint32_t* dst, float4 v) {
    dst[0] = f2tf32(v.x); dst[1] = f2tf32(v.y);
    dst[2] = f2tf32(v.z); dst[3] = f2tf32(v.w);
}
__device__ __forceinline__ void mma_f16(float* c, const uint32_t* a, const uint32_t* b) {
    asm volatile(
        "mma.sync.aligned.m16n8k16.row.col.f32.f16.f16.f32 "
        "{%0,%1,%2,%3}, {%4,%5,%6,%7}, {%8,%9}, {%0,%1,%2,%3};\n"
        : "+f"(c[0]), "+f"(c[1]), "+f"(c[2]), "+f"(c[3])
        : "r"(a[0]), "r"(a[1]), "r"(a[2]), "r"(a[3]), "r"(b[0]), "r"(b[1]));
}
__device__ __forceinline__ void mma_tf32(float* c, const uint32_t* a, const uint32_t* b) {
    asm volatile(
        "mma.sync.aligned.m16n8k8.row.col.f32.tf32.tf32.f32 "
        "{%0,%1,%2,%3}, {%4,%5,%6,%7}, {%8,%9}, {%0,%1,%2,%3};\n"
        : "+f"(c[0]), "+f"(c[1]), "+f"(c[2]), "+f"(c[3])
        : "r"(a[0]), "r"(a[1]), "r"(a[2]), "r"(a[3]), "r"(b[0]), "r"(b[1]));
}
__device__ __forceinline__ uint32_t smem_u32(const void* p) {
    uint32_t a;
    asm("{ .reg .u64 t; cvta.to.shared.u64 t, %1; cvt.u32.u64 %0, t; }" : "=r"(a) : "l"(p));
    return a;
}
__device__ __forceinline__ uint32_t swz128(uint32_t o) { return o ^ ((o >> 3) & 0x70); }
__device__ __forceinline__ void cp16(uint32_t dst, const void* src) {
    asm volatile("cp.async.cg.shared.global [%0], [%1], 16;\n" :: "r"(dst), "l"(src) : "memory");
}
__device__ __forceinline__ void bulkN(uint32_t dst, const void* src, uint32_t n, uint32_t mbar) {
    asm volatile(
        "cp.async.bulk.shared::cluster.global.mbarrier::complete_tx::bytes [%0], [%1], %2, [%3];"
        :: "r"(dst), "l"(src), "r"(n), "r"(mbar) : "memory");
}
#define MBARRIER_INIT(mbar, count) \
    asm volatile("mbarrier.init.shared.b64 [%0], %1;" :: "r"((uint32_t)(mbar)), "r"((uint32_t)(count)) : "memory")
#define MBARRIER_EXPECT_TX(mbar, tx) \
    asm volatile("mbarrier.arrive.expect_tx.shared.b64 _, [%0], %1;" :: "r"((uint32_t)(mbar)), "r"((uint32_t)(tx)) : "memory")
#define MBARRIER_WAIT_PARITY(mbar, parity) do { \
    uint32_t _m = (uint32_t)(mbar); uint32_t _p = (uint32_t)(parity); uint32_t _d; \
    asm volatile("{\n\t.reg .pred p;\n\t" \
        "mbarrier.try_wait.parity.acquire.cta.shared::cta.b64 p, [%1], %2;\n\t" \
        "selp.b32 %0, 1, 0, p;\n\t}" : "=r"(_d) : "r"(_m), "r"(_p) : "memory"); \
    if (!_d) { \
        asm volatile("{\n\t.reg .pred P1;\n\t" \
            "WL_%=:\n\t" \
            "mbarrier.try_wait.parity.acquire.cta.shared::cta.b64 P1, [%0], %1, 0x989680;\n\t" \
            "@P1 bra.uni WD_%=;\n\t" \
            "bra.uni WL_%=;\n\t" \
            "WD_%=:\n\t}" :: "r"(_m), "r"(_p) : "memory"); \
    } \
} while (0)
#define LDSM4(r0, r1, r2, r3, addr) \
    asm volatile("ldmatrix.sync.aligned.m8n8.x4.shared.b16 {%0,%1,%2,%3}, [%4];" \
                 : "=r"(r0), "=r"(r1), "=r"(r2), "=r"(r3) : "r"(addr))

// ---------------- weight fp16 conversion ----------------
__global__ void conv_k(const float* __restrict__ src, __half* __restrict__ dst, int n8) {
    int i = blockIdx.x * 256 + threadIdx.x;
    if (i < n8) {
        float4 a = ((const float4*)src)[2 * i];
        float4 b = ((const float4*)src)[2 * i + 1];
        uint4 u;
        u.x = pack2(a.x, a.y); u.y = pack2(a.z, a.w);
        u.z = pack2(b.x, b.y); u.w = pack2(b.z, b.w);
        ((uint4*)dst)[i] = u;
    }
}
__global__ void conv_slice_k(const float* __restrict__ src, __half* __restrict__ dst) {
    int r = blockIdx.x;
    float4 v = ((const float4*)(src + (size_t)r * (DEMB + H)))[threadIdx.x];
    uint2 u; u.x = pack2(v.x, v.y); u.y = pack2(v.z, v.w);
    ((uint2*)(dst + (size_t)r * DEMB))[threadIdx.x] = u;
}

// ---------------- lin_W fragment-major permute (fp32 -> fp16), nbg-major kcg-minor ----------------
__global__ void permute_wl_k(const float* __restrict__ W, uint4* __restrict__ Bp) {
    int w = (blockIdx.x * blockDim.x + threadIdx.x) >> 5;
    int lane = threadIdx.x & 31;
    int nbg = w >> 6, kcg = w & 63;
    int row0 = nbg * 16 + (lane >> 2);
    int col0 = kcg * 16 + (lane & 3) * 2;
    const float* p00 = W + (size_t)row0 * H + col0;
    const float* p10 = W + (size_t)(row0 + 8) * H + col0;
    float2 v00 = *(const float2*)(p00);
    float2 v10 = *(const float2*)(p10);
    float2 v01 = *(const float2*)(p00 + 8);
    float2 v11 = *(const float2*)(p10 + 8);
    uint4 o;
    o.x = pack2(v00.x, v00.y);
    o.y = pack2(v10.x, v10.y);
    o.z = pack2(v01.x, v01.y);
    o.w = pack2(v11.x, v11.y);
    Bp[(size_t)w * 32 + lane] = o;
}

// ---------------- embedding gathers -> fp16 ----------------
__global__ void embed_enc_k(const int* __restrict__ x, const float* __restrict__ emb,
                            __half* __restrict__ Xe) {
    int row = blockIdx.x;
    int t = row >> 6, b = row & 63;
    int tok = x[b * TENC + t];
    float4 v = ((const float4*)(emb + (size_t)tok * DEMB))[threadIdx.x];
    uint2 u; u.x = pack2(v.x, v.y); u.y = pack2(v.z, v.w);
    ((uint2*)(Xe + (size_t)row * DEMB))[threadIdx.x] = u;
}
__global__ void embed_dec_k(const int* __restrict__ labels, const int* __restrict__ bos,
                            const float* __restrict__ emb, __half* __restrict__ Xw) {
    int row = blockIdx.x;
    int t = row >> 6, b = row & 63;
    int tok = (t == 0) ? bos[0] : labels[b * TDEC + t - 1];
    float4 v = ((const float4*)(emb + (size_t)tok * DEMB))[threadIdx.x];
    uint2 u; u.x = pack2(v.x, v.y); u.y = pack2(v.z, v.w);
    ((uint2*)(Xw + (size_t)row * DEMB))[threadIdx.x] = u;
}

__global__ void init_all_k(float* __restrict__ h0f, __half* __restrict__ h0h,
                           float* __restrict__ hd0f, __half* __restrict__ hd0h,
                           const float* __restrict__ dec_init) {
    int b = blockIdx.x, u = threadIdx.x;
    h0f[b * H + u] = 0.0f;
    h0h[b * H + u] = __float2half_rn(0.0f);
    float di = dec_init[u];
    hd0f[b * H + u] = di;
    hd0h[b * H + u] = __float2half_rn(di);
    if (b == 0 && u == 0) { g_bar_cnt = 0; g_bar_gen = 0; }
}

// ---------------- fp16 GEMM (Xi/Xd): round-10 proven path ----------------
__global__ __launch_bounds__(512, 1)
void gemm_f16_k(const __half* __restrict__ A, const __half* __restrict__ B,
                const float* __restrict__ bias, float* __restrict__ C,
                int N, int K) {
    extern __shared__ char smc[];
    const uint32_t sb = smem_u32(smc);
    const int m0 = blockIdx.x * 128, n0 = blockIdx.y * 256;
    const int tid = threadIdx.x, lane = tid & 31, wid = tid >> 5;
    const int wr = wid >> 2, wc = wid & 3;
    const int g = lane >> 2, tg = lane & 3;

    float acc[2][8][4];
#pragma unroll
    for (int ms = 0; ms < 2; ms++)
#pragma unroll
        for (int ns = 0; ns < 8; ns++)
#pragma unroll
            for (int i = 0; i < 4; i++) acc[ms][ns][i] = 0.0f;

    const __half* Ab = A + (size_t)m0 * K;
    const __half* Bb = B + (size_t)n0 * K;

    auto load_stage = [&](int s, int k0) {
        uint32_t sbase = sb + s * GSTG;
#pragma unroll
        for (int i = 0; i < 2; i++) {
            int idx = tid + i * 512;
            int row = idx >> 3, c = idx & 7;
            cp16(sbase + swz128(row * 128 + c * 16), Ab + (size_t)row * K + k0 + c * 8);
        }
#pragma unroll
        for (int i = 0; i < 4; i++) {
            int idx = tid + i * 512;
            int row = idx >> 3, c = idx & 7;
            cp16(sbase + 16384 + swz128(row * 128 + c * 16), Bb + (size_t)row * K + k0 + c * 8);
        }
        asm volatile("cp.async.commit_group;\n" ::: "memory");
    };

    const int NT = K >> 6;
    load_stage(0, 0);
    load_stage(1, 64);

    const int r16 = lane & 15, chb = (lane >> 4) << 4;

    for (int it = 0; it < NT; ++it) {
        const int s = it % 3;
        if (it == NT - 1) asm volatile("cp.async.wait_group 0;\n" ::: "memory");
        else              asm volatile("cp.async.wait_group 1;\n" ::: "memory");
        __syncthreads();
        if (it + 2 < NT) load_stage((it + 2) % 3, (it + 2) * 64);

        const uint32_t sA = sb + s * GSTG;
        const uint32_t sB = sA + 16384;
#pragma unroll
        for (int kk = 0; kk < 4; kk++) {
            const int kb = kk * 32 + chb;
            uint32_t a[2][4], b[8][2];
#pragma unroll
            for (int ms = 0; ms < 2; ms++) {
                uint32_t ad = sA + swz128(((wr * 32 + ms * 16 + r16) << 7) + kb);
                LDSM4(a[ms][0], a[ms][1], a[ms][2], a[ms][3], ad);
            }
#pragma unroll
            for (int np = 0; np < 4; np++) {
                uint32_t bd = sB + swz128(((wc * 64 + np * 16 + r16) << 7) + kb);
                uint32_t r0, r1, r2, r3;
                LDSM4(r0, r1, r2, r3, bd);
                b[2 * np][0] = r0; b[2 * np + 1][0] = r1;
                b[2 * np][1] = r2; b[2 * np + 1][1] = r3;
            }
#pragma unroll
            for (int ms = 0; ms < 2; ms++)
#pragma unroll
                for (int ns = 0; ns < 8; ns++)
                    mma_f16(acc[ms][ns], a[ms], b[ns]);
        }
        __syncthreads();
    }

#pragma unroll
    for (int ms = 0; ms < 2; ms++)
#pragma unroll
        for (int ns = 0; ns < 8; ns++) {
            int row = m0 + wr * 32 + ms * 16 + g;
            int col = n0 + wc * 64 + ns * 8 + 2 * tg;
            float b0 = bias[col], b1 = bias[col + 1];
#pragma unroll
            for (int h2 = 0; h2 < 2; h2++) {
                int r = row + h2 * 8;
                size_t idx = (size_t)r * (size_t)N + col;
                float2 v;
                v.x = acc[ms][ns][h2 * 2 + 0] + b0;
                v.y = acc[ms][ns][h2 * 2 + 1] + b1;
                *(float2*)(C + idx) = v;
            }
        }
}

// ---------------- logits GEMM: A cp.async + B fragment-major via cp.async.bulk ----------------
// BM=128, BN=256, BK=64, K=1024. 512 threads: wr=wid>>3 (m 2x64), wc=wid&7 (n 8x32).
// B smem stage layout: nl (0..15) * 2048 + kc*512 + lane*16. Output transposed.
__global__ __launch_bounds__(512, 1)
void gemm_logits_k(const __half* __restrict__ A, const uint4* __restrict__ Bp,
                   const float* __restrict__ bias, float* __restrict__ C) {
    extern __shared__ char smc[];
    const uint32_t sb = smem_u32(smc);
    const uint32_t MB = sb + 3 * LG_STG;
    const int m0 = blockIdx.x * 128, n0 = blockIdx.y * 256;
    const int tid = threadIdx.x, lane = tid & 31, wid = tid >> 5;
    const int wr = wid >> 3, wc = wid & 7;
    const int g = lane >> 2, tg = lane & 3;

    float acc[4][4][4];
#pragma unroll
    for (int ms = 0; ms < 4; ms++)
#pragma unroll
        for (int j = 0; j < 4; j++)
#pragma unroll
            for (int i = 0; i < 4; i++) acc[ms][j][i] = 0.0f;

    const __half* Ab = A + (size_t)m0 * H;
    const char* Bpb = (const char*)Bp + ((size_t)(n0 >> 4) * KC_LOG) * 512;

    if (tid == 0) {
        MBARRIER_INIT(MB + 0, 1);
        MBARRIER_INIT(MB + 8, 1);
        MBARRIER_INIT(MB + 16, 1);
    }
    __syncthreads();

    auto issue_stage = [&](int s, int it) {
        uint32_t sbase = sb + s * LG_STG;
        const int k0 = it * 64;
#pragma unroll
        for (int i = 0; i < 2; i++) {
            int idx = tid + i * 512;
            int row = idx >> 3, c = idx & 7;
            cp16(sbase + swz128(row * 128 + c * 16), Ab + (size_t)row * H + k0 + c * 8);
        }
        asm volatile("cp.async.commit_group;\n" ::: "memory");
        if (tid == 0) {
            uint32_t mb = MB + s * 8;
            MBARRIER_EXPECT_TX(mb, (uint32_t)LG_BSTG);
            uint32_t bdst = sbase + LG_ASTG;
#pragma unroll
            for (int nl = 0; nl < 16; nl++) {
                bulkN(bdst + nl * 2048,
                      Bpb + ((size_t)nl * KC_LOG + it * 4) * 512,
                      2048u, mb);
            }
        }
    };

    const int NT = H >> 6;   // 16
    issue_stage(0, 0);
    issue_stage(1, 1);

    const int r16 = lane & 15, chb = (lane >> 4) << 4;

    for (int it = 0; it < NT; ++it) {
        const int s = it % 3;
        if (it == NT - 1) asm volatile("cp.async.wait_group 0;\n" ::: "memory");
        else              asm volatile("cp.async.wait_group 1;\n" ::: "memory");
        MBARRIER_WAIT_PARITY(MB + s * 8, (it / 3) & 1);
        __syncthreads();
        if (it + 2 < NT) issue_stage((it + 2) % 3, it + 2);

        const uint32_t sA = sb + s * LG_STG;
        const uint32_t sB = sA + LG_ASTG + (wc * 2) * 2048 + lane * 16;
#pragma unroll
        for (int kc = 0; kc < 4; kc++) {
            const int kb = kc * 32 + chb;
            uint32_t a[4][4];
#pragma unroll
            for (int ms = 0; ms < 4; ms++) {
                uint32_t ad = sA + swz128(((wr * 64 + ms * 16 + r16) << 7) + kb);
                LDSM4(a[ms][0], a[ms][1], a[ms][2], a[ms][3], ad);
            }
            uint4 cb0 = *(const uint4*)(size_t)0;  // placeholder removed below
            // load B fragments from smem (lane's uint4 per nbg)
            uint4 b0, b1;
            asm volatile("ld.shared.v4.u32 {%0,%1,%2,%3}, [%4];"
                         : "=r"(b0.x), "=r"(b0.y), "=r"(b0.z), "=r"(b0.w)
                         : "r"(sB + kc * 512));
            asm volatile("ld.shared.v4.u32 {%0,%1,%2,%3}, [%4];"
                         : "=r"(b1.x), "=r"(b1.y), "=r"(b1.z), "=r"(b1.w)
                         : "r"(sB + 2048 + kc * 512));
            uint32_t b[4][2];
            b[0][0] = b0.x; b[0][1] = b0.z;
            b[1][0] = b0.y; b[1][1] = b0.w;
            b[2][0] = b1.x; b[2][1] = b1.z;
            b[3][0] = b1.y; b[3][1] = b1.w;
#pragma unroll
            for (int ms = 0; ms < 4; ms++)
#pragma unroll
                for (int j = 0; j < 4; j++)
                    mma_f16(acc[ms][j], a[ms], b[j]);
        }
        __syncthreads();
    }

#pragma unroll
    for (int ms = 0; ms < 4; ms++)
#pragma unroll
        for (int j = 0; j < 4; j++) {
            int row = m0 + wr * 64 + ms * 16 + g;
            int col = n0 + wc * 32 + j * 8 + 2 * tg;
            float b0 = bias[col], b1 = bias[col + 1];
#pragma unroll
            for (int h2 = 0; h2 < 2; h2++) {
                int r = row + h2 * 8;
                int bb = r & 63, tt = r >> 6;
                size_t idx = ((size_t)bb * TDEC + tt) * (size_t)VOCAB + col;
                float2 v;
                v.x = acc[ms][j][h2 * 2 + 0] + b0;
                v.y = acc[ms][j][h2 * 2 + 1] + b1;
                *(float2*)(C + idx) = v;
            }
        }
}

// ---------------- small tf32 GEMM (ctx only: 64 x 3072 x 1024) ----------------
__global__ __launch_bounds__(256, 2)
void gemm_tf32_k(const float* __restrict__ A, int lda,
                 const float* __restrict__ W, int ldw, int koff,
                 float* __restrict__ C, int M, int N, int K) {
    __shared__ uint32_t As[128][20];
    __shared__ uint32_t Bs[128][20];
    const int m0 = blockIdx.x * 128, n0 = blockIdx.y * 128;
    const int tid = threadIdx.x, lane = tid & 31, wid = tid >> 5;
    const int wr = wid >> 1, wc = wid & 1;
    const int g = lane >> 2, tg = lane & 3;
    float acc[2][8][4];
#pragma unroll
    for (int ms = 0; ms < 2; ms++)
#pragma unroll
        for (int ns = 0; ns < 8; ns++)
#pragma unroll
            for (int i = 0; i < 4; i++) acc[ms][ns][i] = 0.0f;
    const int lrow = tid >> 1, lcol = (tid & 1) * 8;
    const float* Ap = A + (size_t)(m0 + lrow) * lda + lcol;
    const float* Wp = W + (size_t)(n0 + lrow) * ldw + koff + lcol;
    const bool aok = (m0 + lrow) < M;
    for (int k0 = 0; k0 < K; k0 += 16) {
        if (aok) {
            cvt_store4(&As[lrow][lcol], *(const float4*)(Ap + k0));
            cvt_store4(&As[lrow][lcol + 4], *(const float4*)(Ap + k0 + 4));
        } else {
#pragma unroll
            for (int i = 0; i < 8; i++) As[lrow][lcol + i] = 0u;
        }
        cvt_store4(&Bs[lrow][lcol], *(const float4*)(Wp + k0));
        cvt_store4(&Bs[lrow][lcol + 4], *(const float4*)(Wp + k0 + 4));
        __syncthreads();
#pragma unroll
        for (int kk = 0; kk < 16; kk += 8) {
            uint32_t a[2][4], b[8][2];
#pragma unroll
            for (int ms = 0; ms < 2; ms++) {
                int r0 = wr * 32 + ms * 16 + g;
                a[ms][0] = As[r0][kk + tg]; a[ms][1] = As[r0 + 8][kk + tg];
                a[ms][2] = As[r0][kk + tg + 4]; a[ms][3] = As[r0 + 8][kk + tg + 4];
            }
#pragma unroll
            for (int ns = 0; ns < 8; ns++) {
                int br = wc * 64 + ns * 8 + g;
                b[ns][0] = Bs[br][kk + tg]; b[ns][1] = Bs[br][kk + tg + 4];
            }
#pragma unroll
            for (int ms = 0; ms < 2; ms++)
#pragma unroll
                for (int ns = 0; ns < 8; ns++) mma_tf32(acc[ms][ns], a[ms], b[ns]);
        }
        __syncthreads();
    }
#pragma unroll
    for (int ms = 0; ms < 2; ms++)
#pragma unroll
        for (int ns = 0; ns < 8; ns++) {
            int row = m0 + wr * 32 + ms * 16 + g;
            int col = n0 + wc * 64 + ns * 8 + 2 * tg;
#pragma unroll
            for (int h2 = 0; h2 < 2; h2++) {
                int r = row + h2 * 8;
                if (r < M) {
                    size_t idx = (size_t)r * (size_t)N + col;
                    float2 v;
                    v.x = acc[ms][ns][h2 * 2 + 0];
                    v.y = acc[ms][ns][h2 * 2 + 1];
                    *(float2*)(C + idx) = v;
                }
            }
        }
}

// ---------------- persistent GRU recurrence: 128 CTAs x 8 hidden units ----------------
template <bool DEC>
__global__ __launch_bounds__(256, 1)
void gru_persistent_k(float* __restrict__ h0f, float* __restrict__ h1f,
                      __half* __restrict__ h0h, __half* __restrict__ h1h,
                      const float* __restrict__ Whh, const float* __restrict__ bhh,
                      const float* __restrict__ gi, const float* __restrict__ ctx,
                      __half* __restrict__ st, int T) {
    extern __shared__ uint32_t sm[];
    uint32_t* Wsh = sm;
    uint32_t* Ash = sm + 24 * W2S;
    float* Gsh = (float*)(sm + 24 * W2S);

    const int u0 = blockIdx.x * 8;
    const int tid = threadIdx.x, lane = tid & 31, wid = tid >> 5;
    const int kg = wid >> 1, mg = wid & 1;
    const int g = lane >> 2, tg = lane & 3;

    for (int j = 0; j < 24; j++) {
        int grow = (j >> 3) * H + u0 + (j & 7);
        float4 v = *(const float4*)(Whh + (size_t)grow * H + tid * 4);
        Wsh[j * W2S + tid * 2]     = pack2(v.x, v.y);
        Wsh[j * W2S + tid * 2 + 1] = pack2(v.z, v.w);
    }
    const int sr = tid >> 2, q = tid & 3;
    const int gb0 = tid >> 3, gu0 = tid & 7;
    const int gb1 = (tid + 256) >> 3, gu1 = (tid + 256) & 7;

    float bR0 = bhh[u0 + gu0], bZ0 = bhh[H + u0 + gu0], bN0 = bhh[2 * H + u0 + gu0];
    float bR1 = bhh[u0 + gu1], bZ1 = bhh[H + u0 + gu1], bN1 = bhh[2 * H + u0 + gu1];
    float cN0 = 0.0f, cN1 = 0.0f;
    if (DEC) {
        bR0 += ctx[(size_t)gb0 * 3 * H + u0 + gu0];
        bZ0 += ctx[(size_t)gb0 * 3 * H + H + u0 + gu0];
        cN0  = ctx[(size_t)gb0 * 3 * H + 2 * H + u0 + gu0];
        bR1 += ctx[(size_t)gb1 * 3 * H + u0 + gu1];
        bZ1 += ctx[(size_t)gb1 * 3 * H + H + u0 + gu1];
        cN1  = ctx[(size_t)gb1 * 3 * H + 2 * H + u0 + gu1];
    }

    for (int t = 0; t < T; t++) {
        const float* hinf = (t & 1) ? h1f : h0f;
        const __half* hinh = (t & 1) ? h1h : h0h;
        float* houtf = (t & 1) ? h0f : h1f;
        __half* houth = (t & 1) ? h0h : h1h;
        const float* gi_t = gi + (size_t)t * BATCH * 3 * H;

        float pR0 = gi_t[(size_t)gb0 * 3 * H + u0 + gu0];
        float pZ0 = gi_t[(size_t)gb0 * 3 * H + H + u0 + gu0];
        float pN0 = gi_t[(size_t)gb0 * 3 * H + 2 * H + u0 + gu0];
        float pR1 = gi_t[(size_t)gb1 * 3 * H + u0 + gu1];
        float pZ1 = gi_t[(size_t)gb1 * 3 * H + H + u0 + gu1];
        float pN1 = gi_t[(size_t)gb1 * 3 * H + 2 * H + u0 + gu1];
        float hc0 = hinf[(size_t)gb0 * H + u0 + gu0];
        float hc1 = hinf[(size_t)gb1 * H + u0 + gu1];

        uint4 p[4];
        {
            const uint4* src = (const uint4*)(hinh + (size_t)sr * H + q * 32);
#pragma unroll
            for (int i = 0; i < 4; i++) p[i] = src[i];
        }

        float acc[2][3][4];
#pragma unroll
        for (int ms = 0; ms < 2; ms++)
#pragma unroll
            for (int ns = 0; ns < 3; ns++)
#pragma unroll
                for (int i = 0; i < 4; i++) acc[ms][ns][i] = 0.0f;

        for (int c = 0; c < 8; c++) {
            uint32_t* Ab = Ash + (c & 1) * 64 * A2S;
            {
                uint4* dst = (uint4*)(Ab + sr * A2S + q * 16);
#pragma unroll
                for (int i = 0; i < 4; i++) dst[i] = p[i];
            }
            __syncthreads();
            if (c < 7) {
                const uint4* src = (const uint4*)(hinh + (size_t)sr * H + (c + 1) * 128 + q * 32);
#pragma unroll
                for (int i = 0; i < 4; i++) p[i] = src[i];
            }
#pragma unroll
            for (int s = 0; s < 2; s++) {
                const int c0 = kg * 16 + s * 8;
                const int wc0 = c * 64 + kg * 16 + s * 8;
                uint32_t a[2][4], b[3][2];
#pragma unroll
                for (int ms = 0; ms < 2; ms++) {
                    int row = mg * 32 + ms * 16 + g;
                    a[ms][0] = Ab[row * A2S + c0 + tg];
                    a[ms][1] = Ab[(row + 8) * A2S + c0 + tg];
                    a[ms][2] = Ab[row * A2S + c0 + tg + 4];
                    a[ms][3] = Ab[(row + 8) * A2S + c0 + tg + 4];
                }
#pragma unroll
                for (int ns = 0; ns < 3; ns++) {
                    int br = ns * 8 + g;
                    b[ns][0] = Wsh[br * W2S + wc0 + tg];
                    b[ns][1] = Wsh[br * W2S + wc0 + tg + 4];
                }
#pragma unroll
                for (int ms = 0; ms < 2; ms++)
#pragma unroll
                    for (int ns = 0; ns < 3; ns++) mma_f16(acc[ms][ns], a[ms], b[ns]);
            }
        }
        __syncthreads();

#pragma unroll
        for (int ms = 0; ms < 2; ms++)
#pragma unroll
            for (int ns = 0; ns < 3; ns++)
#pragma unroll
                for (int i = 0; i < 4; i++) {
                    int row = mg * 32 + ms * 16 + g + (i >> 1) * 8;
                    int col = ns * 8 + 2 * tg + (i & 1);
                    Gsh[(kg * 64 + row) * G2S + col] = acc[ms][ns][i];
                }
        __syncthreads();

        {
            float aR = 0.f, aZ = 0.f, aN = 0.f;
#pragma unroll
            for (int k = 0; k < 4; k++) {
                const float* Gr = Gsh + (k * 64 + gb0) * G2S;
                aR += Gr[gu0]; aZ += Gr[8 + gu0]; aN += Gr[16 + gu0];
            }
            float rr = 1.0f / (1.0f + __expf(-(pR0 + aR + bR0)));
            float zz = 1.0f / (1.0f + __expf(-(pZ0 + aZ + bZ0)));
            float nn = tanhf(pN0 + cN0 + rr * (aN + bN0));
            float hn = (1.0f - zz) * nn + zz * hc0;
            int u = u0 + gu0;
            houtf[(size_t)gb0 * H + u] = hn;
            __half hh = __float2half_rn(hn);
            houth[(size_t)gb0 * H + u] = hh;
            if (DEC) st[(size_t)t * BATCH * H + (size_t)gb0 * H + u] = hh;
        }
        {
            float aR = 0.f, aZ = 0.f, aN = 0.f;
#pragma unroll
            for (int k = 0; k < 4; k++) {
                const float* Gr = Gsh + (k * 64 + gb1) * G2S;
                aR += Gr[gu1]; aZ += Gr[8 + gu1]; aN += Gr[16 + gu1];
            }
            float rr = 1.0f / (1.0f + __expf(-(pR1 + aR + bR1)));
            float zz = 1.0f / (1.0f + __expf(-(pZ1 + aZ + bZ1)));
            float nn = tanhf(pN1 + cN1 + rr * (aN + bN1));
            float hn = (1.0f - zz) * nn + zz * hc1;
            int u = u0 + gu1;
            houtf[(size_t)gb1 * H + u] = hn;
            __half hh = __float2half_rn(hn);
            houth[(size_t)gb1 * H + u] = hh;
            if (DEC) st[(size_t)t * BATCH * H + (size_t)gb1 * H + u] = hh;
        }

        __threadfence();
        __syncthreads();
        if (tid == 0) {
            unsigned old_gen = *(volatile unsigned*)&g_bar_gen;
            unsigned r = atomicAdd(&g_bar_cnt, 1);
            if (r == GRU_NCTA - 1) {
                atomicExch(&g_bar_cnt, 0);
                __threadfence();
                atomicAdd(&g_bar_gen, 1);
            } else {
                while (*(volatile unsigned*)&g_bar_gen == old_gen) {}
            }
        }
        __syncthreads();
    }
}

// ---------------- host orchestration ----------------
extern "C" void kernel_launch(void* const* d_in, const int* in_sizes, int n_in,
                              void* d_out, int out_size) {
    const int*   x        = (const int*)d_in[0];
    const int*   labels   = (const int*)d_in[1];
    const int*   bos      = (const int*)d_in[2];
    const float* enc_emb  = (const float*)d_in[3];
    const float* enc_Wih  = (const float*)d_in[4];
    const float* enc_Whh  = (const float*)d_in[5];
    const float* enc_bih  = (const float*)d_in[6];
    const float* enc_bhh  = (const float*)d_in[7];
    const float* dec_emb  = (const float*)d_in[8];
    const float* dec_Wih  = (const float*)d_in[9];
    const float* dec_Whh  = (const float*)d_in[10];
    const float* dec_bih  = (const float*)d_in[11];
    const float* dec_bhh  = (const float*)d_in[12];
    const float* dec_init = (const float*)d_in[13];
    const float* lin_W    = (const float*)d_in[14];
    const float* lin_b    = (const float*)d_in[15];
    float*       out      = (float*)d_out;

    __half *Xe, *Xw, *st, *We, *Wd, *Wl, *h0h, *h1h, *hd0h, *hd1h;
    float *Xi, *Xd, *ctx, *h0f, *h1f, *hd0f, *hd1f;
    cudaGetSymbolAddress((void**)&Xe, g_Xe);
    cudaGetSymbolAddress((void**)&Xi, g_Xi);
    cudaGetSymbolAddress((void**)&Xw, g_Xw);
    cudaGetSymbolAddress((void**)&Xd, g_Xd);
    cudaGetSymbolAddress((void**)&ctx, g_ctx);
    cudaGetSymbolAddress((void**)&h0f, g_h0f);
    cudaGetSymbolAddress((void**)&h1f, g_h1f);
    cudaGetSymbolAddress((void**)&h0h, g_h0h);
    cudaGetSymbolAddress((void**)&h1h, g_h1h);
    cudaGetSymbolAddress((void**)&hd0f, g_hd0f);
    cudaGetSymbolAddress((void**)&hd1f, g_hd1f);
    cudaGetSymbolAddress((void**)&hd0h, g_hd0h);
    cudaGetSymbolAddress((void**)&hd1h, g_hd1h);
    cudaGetSymbolAddress((void**)&st, g_st);
    cudaGetSymbolAddress((void**)&We, g_We);
    cudaGetSymbolAddress((void**)&Wd, g_Wd);
    cudaGetSymbolAddress((void**)&Wl, g_Wl);

    cudaFuncSetAttribute(gru_persistent_k<false>,
                         cudaFuncAttributeMaxDynamicSharedMemorySize, GRU_SMEM_BYTES);
    cudaFuncSetAttribute(gru_persistent_k<true>,
                         cudaFuncAttributeMaxDynamicSharedMemorySize, GRU_SMEM_BYTES);
    cudaFuncSetAttribute(gemm_f16_k,
                         cudaFuncAttributeMaxDynamicSharedMemorySize, GEMM_SMEM_BYTES);
    cudaFuncSetAttribute(gemm_logits_k,
                         cudaFuncAttributeMaxDynamicSharedMemorySize, LG_SMEM);

    // ---- weight prep ----
    conv_k<<<(3 * H * DEMB / 8 + 255) / 256, 256>>>(enc_Wih, We, 3 * H * DEMB / 8);
    conv_slice_k<<<3 * H, 128>>>(dec_Wih, Wd);
    permute_wl_k<<<(VOCAB / 16) * KC_LOG / 8, 256>>>(lin_W, (uint4*)Wl);

    // ---- encoder ----
    embed_enc_k<<<TENC * BATCH, 128>>>(x, enc_emb, Xe);
    init_all_k<<<BATCH, H>>>(h0f, h0h, hd0f, hd0h, dec_init);
    gemm_f16_k<<<dim3(TENC * BATCH / 128, 3 * H / 256), 512, GEMM_SMEM_BYTES>>>(
        Xe, We, enc_bih, Xi, 3 * H, DEMB);
    gru_persistent_k<false><<<GRU_NCTA, 256, GRU_SMEM_BYTES>>>(
        h0f, h1f, h0h, h1h, enc_Whh, enc_bhh, Xi, nullptr, nullptr, TENC);
    float* efin = h0f;

    // ---- decoder precompute ----
    embed_dec_k<<<TDEC * BATCH, 128>>>(labels, bos, dec_emb, Xw);
    gemm_f16_k<<<dim3(TDEC * BATCH / 128, 3 * H / 256), 512, GEMM_SMEM_BYTES>>>(
        Xw, Wd, dec_bih, Xd, 3 * H, DEMB);
    gemm_tf32_k<<<dim3(1, 24), 256>>>(efin, H, dec_Wih, DEMB + H, DEMB, ctx,
                                      BATCH, 3 * H, H);
    gru_persistent_k<true><<<GRU_NCTA, 256, GRU_SMEM_BYTES>>>(
        hd0f, hd1f, hd0h, hd1h, dec_Whh, dec_bhh, Xd, ctx, st, TDEC);

    // ---- logits ----
    gemm_logits_k<<<dim3(TDEC * BATCH / 128, VOCAB / 256), 512, LG_SMEM>>>(
        st, (const uint4*)Wl, lin_b, out);
}